// round 5
// baseline (speedup 1.0000x reference)
#include <cuda_runtime.h>
#include <math_constants.h>

#define NB     4
#define NSRC   2048
#define NDST   8192
#define CIN    256
#define CSKIP  128
#define CCAT   384
#define HDIM   256
#define COUT   128
#define PDIM   64
#define MTOT   (NB * NDST)          // 32768

#define OUT_ELEMS   (MTOT * COUT)   // 4194304
#define POS_ELEMS   (MTOT * 3)      // 98304

// Scratch (allocation-free rule: __device__ globals)
__device__ float g_xin[MTOT * CCAT];   // 48 MB
__device__ float g_h1[MTOT * HDIM];    // 32 MB
__device__ float g_gate[NB * COUT];

// ---------------------------------------------------------------------------
// gate = relu(par_embedding @ Wp + bp)   (4 x 64) @ (64 x 128)
// ---------------------------------------------------------------------------
__global__ void gate_kernel(const float* __restrict__ par,
                            const float* __restrict__ Wp,
                            const float* __restrict__ bp) {
    int t = threadIdx.x;            // 0..511
    int b = t >> 7;
    int n = t & 127;
    float acc = bp[n];
    const float* pe = par + b * PDIM;
#pragma unroll
    for (int p = 0; p < PDIM; ++p)
        acc = fmaf(pe[p], Wp[p * COUT + n], acc);
    g_gate[b * COUT + n] = fmaxf(acc, 0.0f);
}

// ---------------------------------------------------------------------------
// KNN (k=3) + inverse-squared-distance interpolate + concat x_skip
//
// d2 arithmetic variant A (XLA fmuladd-contracted reductions):
//   src2 = fma(z,z, fma(y,y, rn(x*x)))      ascending fma chain
//   dot  = fma(dz,sz, fma(dy,sy, rn(dx*sx)))  ascending fma chain
//   d2   = rn( rn(dst2 + src2) - rn(2*dot) )  separately rounded combine
// Selection ties broken by lowest source index (lax.top_k stable semantics).
// ---------------------------------------------------------------------------
__device__ __forceinline__ void insert3(float d, int j,
                                        float& b0, float& b1, float& b2,
                                        int& i0, int& i1, int& i2) {
    // strict-better OR equal-with-smaller-index (stable top_k tie-break)
    bool lt2 = (d < b2) || (d == b2 && j < i2);
    if (lt2) {
        bool lt1 = (d < b1) || (d == b1 && j < i1);
        if (lt1) {
            b2 = b1; i2 = i1;
            bool lt0 = (d < b0) || (d == b0 && j < i0);
            if (lt0) { b1 = b0; i1 = i0; b0 = d; i0 = j; }
            else     { b1 = d;  i1 = j; }
        } else { b2 = d; i2 = j; }
    }
}

#define BPB 64                   // blocks per batch
#define DPB (NDST / BPB)         // 128 dst points per block

__global__ __launch_bounds__(256)
void knn_interp_kernel(const float* __restrict__ x,
                       const float* __restrict__ pos,
                       const float* __restrict__ x_skip,
                       const float* __restrict__ pos_skip) {
    __shared__ float sx[NSRC], sy[NSRC], sz[NSRC], s2[NSRC];   // 32 KB
    const int b   = blockIdx.y;
    const int tid = threadIdx.x;

    const float* sp = pos + (size_t)b * NSRC * 3;
    for (int i = tid; i < NSRC; i += 256) {
        float px = sp[i * 3 + 0];
        float py = sp[i * 3 + 1];
        float pz = sp[i * 3 + 2];
        sx[i] = px; sy[i] = py; sz[i] = pz;
        // ascending fma chain: fma(z,z, fma(y,y, rn(x*x)))
        s2[i] = __fmaf_rn(pz, pz, __fmaf_rn(py, py, __fmul_rn(px, px)));
    }
    __syncthreads();

    const int w = tid >> 5;
    const int l = tid & 31;
    const unsigned FULL = 0xffffffffu;

    for (int local = w; local < DPB; local += 8) {
        const int m = b * NDST + blockIdx.x * DPB + local;   // global dst row
        const float dx = pos_skip[m * 3 + 0];
        const float dy = pos_skip[m * 3 + 1];
        const float dz = pos_skip[m * 3 + 2];
        const float dd = __fmaf_rn(dz, dz, __fmaf_rn(dy, dy, __fmul_rn(dx, dx)));

        float b0 = CUDART_INF_F, b1 = CUDART_INF_F, b2 = CUDART_INF_F;
        int   i0 = 0x7fffffff, i1 = 0x7fffffff, i2 = 0x7fffffff;

        for (int j = l; j < NSRC; j += 32) {
            // ascending fma chain: fma(dz,sz, fma(dy,sy, rn(dx*sx)))
            float dot = __fmaf_rn(dz, sz[j],
                        __fmaf_rn(dy, sy[j],
                        __fmul_rn(dx, sx[j])));
            // (dst2 + src2) - 2*dot, separately rounded
            float d2 = __fadd_rn(__fadd_rn(dd, s2[j]),
                                 -__fmul_rn(2.0f, dot));
            insert3(d2, j, b0, b1, b2, i0, i1, i2);
        }

        // warp tree-merge of sorted-3 lists (tie-break by index inside insert3)
        for (int off = 16; off; off >>= 1) {
            float c0 = __shfl_down_sync(FULL, b0, off);
            float c1 = __shfl_down_sync(FULL, b1, off);
            float c2 = __shfl_down_sync(FULL, b2, off);
            int   j0 = __shfl_down_sync(FULL, i0, off);
            int   j1 = __shfl_down_sync(FULL, i1, off);
            int   j2 = __shfl_down_sync(FULL, i2, off);
            insert3(c0, j0, b0, b1, b2, i0, i1, i2);
            insert3(c1, j1, b0, b1, b2, i0, i1, i2);
            insert3(c2, j2, b0, b1, b2, i0, i1, i2);
        }
        b0 = __shfl_sync(FULL, b0, 0);
        b1 = __shfl_sync(FULL, b1, 0);
        b2 = __shfl_sync(FULL, b2, 0);
        i0 = __shfl_sync(FULL, i0, 0);
        i1 = __shfl_sync(FULL, i1, 0);
        i2 = __shfl_sync(FULL, i2, 0);

        // weights exactly as reference: w = 1/max(d2,1e-16), y = num / den
        const float w0 = __fdiv_rn(1.0f, fmaxf(b0, 1e-16f));
        const float w1 = __fdiv_rn(1.0f, fmaxf(b1, 1e-16f));
        const float w2 = __fdiv_rn(1.0f, fmaxf(b2, 1e-16f));
        const float den = __fadd_rn(__fadd_rn(w0, w1), w2);

        const float* x0 = x + ((size_t)b * NSRC + i0) * CIN;
        const float* x1 = x + ((size_t)b * NSRC + i1) * CIN;
        const float* x2 = x + ((size_t)b * NSRC + i2) * CIN;
        float* xo = g_xin + (size_t)m * CCAT;

#pragma unroll
        for (int c = l; c < CIN; c += 32) {
            float num = __fadd_rn(__fadd_rn(__fmul_rn(w0, x0[c]),
                                            __fmul_rn(w1, x1[c])),
                                  __fmul_rn(w2, x2[c]));
            xo[c] = __fdiv_rn(num, den);
        }
        const float* xs = x_skip + (size_t)m * CSKIP;
#pragma unroll
        for (int c = l; c < CSKIP; c += 32)
            xo[CIN + c] = xs[c];
    }
}

// ---------------------------------------------------------------------------
// Tiled fp32 SGEMM: C[M,N] = epilogue(A[M,K] @ W[K,N] + bias)
// Block tile 128x128, BK=8, 256 threads, 8x8 per-thread microtile.
// EPI: 0 -> relu, 1 -> gate multiply (final out)
// ---------------------------------------------------------------------------
template<int N, int K, int EPI>
__global__ __launch_bounds__(256)
void sgemm_kernel(const float* __restrict__ A,
                  const float* __restrict__ W,
                  const float* __restrict__ bias,
                  float* __restrict__ C) {
    __shared__ float As[8][132];
    __shared__ float Bs[8][132];

    const int tid = threadIdx.x;
    const int bm  = blockIdx.y * 128;
    const int bn  = blockIdx.x * 128;

    const int arow = tid >> 1;            // 0..127
    const int acol = (tid & 1) * 4;       // 0 or 4
    const int brow = tid >> 5;            // 0..7
    const int bcol = (tid & 31) * 4;      // 0..124

    const int tr = tid >> 4;              // 0..15  (M frag)
    const int tc = tid & 15;              // 0..15  (N frag)

    float acc[8][8];
#pragma unroll
    for (int i = 0; i < 8; ++i)
#pragma unroll
        for (int j = 0; j < 8; ++j) acc[i][j] = 0.0f;

    for (int k0 = 0; k0 < K; k0 += 8) {
        float4 av = *(const float4*)&A[(size_t)(bm + arow) * K + k0 + acol];
        float4 bv = *(const float4*)&W[(size_t)(k0 + brow) * N + bn + bcol];

        As[acol + 0][arow] = av.x;
        As[acol + 1][arow] = av.y;
        As[acol + 2][arow] = av.z;
        As[acol + 3][arow] = av.w;
        *(float4*)&Bs[brow][bcol] = bv;
        __syncthreads();

#pragma unroll
        for (int k = 0; k < 8; ++k) {
            float4 a0 = *(const float4*)&As[k][tr * 4];
            float4 a1 = *(const float4*)&As[k][64 + tr * 4];
            float4 c0 = *(const float4*)&Bs[k][tc * 4];
            float4 c1 = *(const float4*)&Bs[k][64 + tc * 4];
            float a[8] = {a0.x, a0.y, a0.z, a0.w, a1.x, a1.y, a1.z, a1.w};
            float bb[8] = {c0.x, c0.y, c0.z, c0.w, c1.x, c1.y, c1.z, c1.w};
#pragma unroll
            for (int i = 0; i < 8; ++i)
#pragma unroll
                for (int j = 0; j < 8; ++j)
                    acc[i][j] = fmaf(a[i], bb[j], acc[i][j]);
        }
        __syncthreads();
    }

    // epilogue
    float bias_lo[4], bias_hi[4];
#pragma unroll
    for (int j = 0; j < 4; ++j) {
        bias_lo[j] = bias[bn + tc * 4 + j];
        bias_hi[j] = bias[bn + 64 + tc * 4 + j];
    }

#pragma unroll
    for (int i = 0; i < 8; ++i) {
        const int mlocal = (i < 4) ? (tr * 4 + i) : (64 + tr * 4 + (i - 4));
        const int m = bm + mlocal;
        float4 lo, hi;
        float* plo = &lo.x;
        float* phi = &hi.x;
#pragma unroll
        for (int j = 0; j < 4; ++j) {
            float vlo = acc[i][j]     + bias_lo[j];
            float vhi = acc[i][j + 4] + bias_hi[j];
            if (EPI == 0) {
                vlo = fmaxf(vlo, 0.0f);
                vhi = fmaxf(vhi, 0.0f);
            } else {
                const int batch = m >> 13;   // m / NDST
                vlo *= g_gate[batch * COUT + bn + tc * 4 + j];
                vhi *= g_gate[batch * COUT + bn + 64 + tc * 4 + j];
            }
            plo[j] = vlo;
            phi[j] = vhi;
        }
        *(float4*)&C[(size_t)m * N + bn + tc * 4]      = lo;
        *(float4*)&C[(size_t)m * N + bn + 64 + tc * 4] = hi;
    }
}

// ---------------------------------------------------------------------------
// Tail: reproduce pos_skip and batch_skip into the concatenated output.
// mode 1: batch as float32 (1 slot each); mode 2: batch as raw int64 (2 slots)
// ---------------------------------------------------------------------------
__global__ void tail_kernel(const float* __restrict__ pos_skip,
                            float* __restrict__ out, int mode, int out_size) {
    int i = blockIdx.x * 256 + threadIdx.x;
    if (i < POS_ELEMS && OUT_ELEMS + i < out_size)
        out[OUT_ELEMS + i] = pos_skip[i];
    if (i < MTOT) {
        if (mode == 1) {
            int o = OUT_ELEMS + POS_ELEMS + i;
            if (o < out_size) out[o] = (float)(i >> 13);
        } else if (mode == 2) {
            int o = OUT_ELEMS + POS_ELEMS + 2 * i;
            if (o + 1 < out_size)
                ((long long*)(out + OUT_ELEMS + POS_ELEMS))[i] = (long long)(i >> 13);
        }
    }
}

// ---------------------------------------------------------------------------
extern "C" void kernel_launch(void* const* d_in, const int* in_sizes, int n_in,
                              void* d_out, int out_size) {
    const float* par      = (const float*)d_in[0];
    const float* x        = (const float*)d_in[1];
    const float* pos      = (const float*)d_in[2];
    const float* x_skip   = (const float*)d_in[3];
    const float* pos_skip = (const float*)d_in[4];
    const float* W1       = (const float*)d_in[5];
    const float* b1       = (const float*)d_in[6];
    const float* W2       = (const float*)d_in[7];
    const float* b2       = (const float*)d_in[8];
    const float* Wp       = (const float*)d_in[9];
    const float* bp       = (const float*)d_in[10];
    float* out = (float*)d_out;

    float* p_xin = nullptr;
    float* p_h1  = nullptr;
    cudaGetSymbolAddress((void**)&p_xin, g_xin);
    cudaGetSymbolAddress((void**)&p_h1,  g_h1);

    gate_kernel<<<1, 512>>>(par, Wp, bp);

    dim3 kg(BPB, NB);
    knn_interp_kernel<<<kg, 256>>>(x, pos, x_skip, pos_skip);

    dim3 g1(HDIM / 128, MTOT / 128);       // (2, 256)
    sgemm_kernel<HDIM, CCAT, 0><<<g1, 256>>>(p_xin, W1, b1, p_h1);

    dim3 g2(COUT / 128, MTOT / 128);       // (1, 256)
    sgemm_kernel<COUT, HDIM, 1><<<g2, 256>>>(p_h1, W2, b2, out);

    const int tail = out_size - OUT_ELEMS;
    if (tail > 0) {
        int mode = 0;
        if (tail >= POS_ELEMS + 2 * MTOT)      mode = 2;
        else if (tail >= POS_ELEMS + MTOT)     mode = 1;
        tail_kernel<<<(POS_ELEMS + 255) / 256, 256>>>(pos_skip, out, mode, out_size);
    }
}

// round 7
// speedup vs baseline: 1.0673x; 1.0673x over previous
#include <cuda_runtime.h>
#include <cuda_bf16.h>
#include <math_constants.h>
#include <cstdint>
#include <mma.h>

using namespace nvcuda;

#define NB     4
#define NSRC   2048
#define NDST   8192
#define CIN    256
#define CSKIP  128
#define CCAT   384
#define HDIM   256
#define COUT   128
#define PDIM   64
#define MTOT   (NB * NDST)          // 32768

#define OUT_ELEMS   (MTOT * COUT)   // 4194304
#define POS_ELEMS   (MTOT * 3)      // 98304

// ---------------------------------------------------------------------------
// Scratch (__device__ globals; no allocations allowed)
// ---------------------------------------------------------------------------
__device__ __nv_bfloat16 g_xin_hi[MTOT * CCAT];   // A1 hi plane, [M,K] K-major
__device__ __nv_bfloat16 g_xin_lo[MTOT * CCAT];
__device__ __nv_bfloat16 g_h1_hi[MTOT * HDIM];    // A2 hi plane
__device__ __nv_bfloat16 g_h1_lo[MTOT * HDIM];
__device__ __nv_bfloat16 g_w1t_hi[HDIM * CCAT];   // B1 [N=256, K=384]
__device__ __nv_bfloat16 g_w1t_lo[HDIM * CCAT];
__device__ __nv_bfloat16 g_w2t_hi[COUT * HDIM];   // B2 [N=128, K=256]
__device__ __nv_bfloat16 g_w2t_lo[COUT * HDIM];
__device__ float g_gate[NB * COUT];

// fp32 -> bf16 hi/lo split
__device__ __forceinline__ void split_bf16(float v, uint16_t& h, uint16_t& l) {
    __nv_bfloat16 hb = __float2bfloat16_rn(v);
    float r = v - __bfloat162float(hb);
    __nv_bfloat16 lb = __float2bfloat16_rn(r);
    h = __bfloat16_as_ushort(hb);
    l = __bfloat16_as_ushort(lb);
}

// ---------------------------------------------------------------------------
// gate = relu(par_embedding @ Wp + bp)
// ---------------------------------------------------------------------------
__global__ void gate_kernel(const float* __restrict__ par,
                            const float* __restrict__ Wp,
                            const float* __restrict__ bp) {
    int t = threadIdx.x;
    int b = t >> 7;
    int n = t & 127;
    float acc = bp[n];
    const float* pe = par + b * PDIM;
#pragma unroll
    for (int p = 0; p < PDIM; ++p)
        acc = fmaf(pe[p], Wp[p * COUT + n], acc);
    g_gate[b * COUT + n] = fmaxf(acc, 0.0f);
}

// ---------------------------------------------------------------------------
// Pre-transpose + split W1 [K,N]->[N,K] hi/lo and W2 likewise
// ---------------------------------------------------------------------------
__global__ void prep_w_kernel(const float* __restrict__ W1,
                              const float* __restrict__ W2) {
    int i = blockIdx.x * 256 + threadIdx.x;
    if (i < CCAT * HDIM) {
        int k = i / HDIM, n = i % HDIM;
        uint16_t h, l;
        split_bf16(W1[i], h, l);
        g_w1t_hi[n * CCAT + k] = __ushort_as_bfloat16(h);
        g_w1t_lo[n * CCAT + k] = __ushort_as_bfloat16(l);
    }
    if (i < HDIM * COUT) {
        int k = i / COUT, n = i % COUT;
        uint16_t h, l;
        split_bf16(W2[i], h, l);
        g_w2t_hi[n * HDIM + k] = __ushort_as_bfloat16(h);
        g_w2t_lo[n * HDIM + k] = __ushort_as_bfloat16(l);
    }
}

// ---------------------------------------------------------------------------
// KNN (k=3) + inverse-squared-distance interpolate + concat x_skip.
// d2 rounding matches the reference bit-exactly (R5-validated):
//   src2/dst2: fma(z,z, fma(y,y, rn(x*x)));  dot: fma chain ascending;
//   d2 = rn(rn(dd+s2) - rn(2*dot)); stable lowest-index tie-break.
// Output written as split-bf16 hi/lo planes for the tensor-core GEMM.
// ---------------------------------------------------------------------------
__device__ __forceinline__ void insert3(float d, int j,
                                        float& b0, float& b1, float& b2,
                                        int& i0, int& i1, int& i2) {
    bool lt2 = (d < b2) || (d == b2 && j < i2);
    if (lt2) {
        bool lt1 = (d < b1) || (d == b1 && j < i1);
        if (lt1) {
            b2 = b1; i2 = i1;
            bool lt0 = (d < b0) || (d == b0 && j < i0);
            if (lt0) { b1 = b0; i1 = i0; b0 = d; i0 = j; }
            else     { b1 = d;  i1 = j; }
        } else { b2 = d; i2 = j; }
    }
}

#define BPB 64
#define DPB (NDST / BPB)

__global__ __launch_bounds__(256)
void knn_interp_kernel(const float* __restrict__ x,
                       const float* __restrict__ pos,
                       const float* __restrict__ x_skip,
                       const float* __restrict__ pos_skip) {
    __shared__ float sx[NSRC], sy[NSRC], sz[NSRC], s2[NSRC];
    const int b   = blockIdx.y;
    const int tid = threadIdx.x;

    const float* sp = pos + (size_t)b * NSRC * 3;
    for (int i = tid; i < NSRC; i += 256) {
        float px = sp[i * 3 + 0];
        float py = sp[i * 3 + 1];
        float pz = sp[i * 3 + 2];
        sx[i] = px; sy[i] = py; sz[i] = pz;
        s2[i] = __fmaf_rn(pz, pz, __fmaf_rn(py, py, __fmul_rn(px, px)));
    }
    __syncthreads();

    const int w = tid >> 5;
    const int l = tid & 31;
    const unsigned FULL = 0xffffffffu;

    for (int local = w; local < DPB; local += 8) {
        const int m = b * NDST + blockIdx.x * DPB + local;
        const float dx = pos_skip[m * 3 + 0];
        const float dy = pos_skip[m * 3 + 1];
        const float dz = pos_skip[m * 3 + 2];
        const float dd = __fmaf_rn(dz, dz, __fmaf_rn(dy, dy, __fmul_rn(dx, dx)));

        float b0 = CUDART_INF_F, b1 = CUDART_INF_F, b2 = CUDART_INF_F;
        int   i0 = 0x7fffffff, i1 = 0x7fffffff, i2 = 0x7fffffff;

        for (int j = l; j < NSRC; j += 32) {
            float dot = __fmaf_rn(dz, sz[j],
                        __fmaf_rn(dy, sy[j],
                        __fmul_rn(dx, sx[j])));
            float d2 = __fadd_rn(__fadd_rn(dd, s2[j]),
                                 -__fmul_rn(2.0f, dot));
            insert3(d2, j, b0, b1, b2, i0, i1, i2);
        }
        for (int off = 16; off; off >>= 1) {
            float c0 = __shfl_down_sync(FULL, b0, off);
            float c1 = __shfl_down_sync(FULL, b1, off);
            float c2 = __shfl_down_sync(FULL, b2, off);
            int   j0 = __shfl_down_sync(FULL, i0, off);
            int   j1 = __shfl_down_sync(FULL, i1, off);
            int   j2 = __shfl_down_sync(FULL, i2, off);
            insert3(c0, j0, b0, b1, b2, i0, i1, i2);
            insert3(c1, j1, b0, b1, b2, i0, i1, i2);
            insert3(c2, j2, b0, b1, b2, i0, i1, i2);
        }
        b0 = __shfl_sync(FULL, b0, 0);
        b1 = __shfl_sync(FULL, b1, 0);
        b2 = __shfl_sync(FULL, b2, 0);
        i0 = __shfl_sync(FULL, i0, 0);
        i1 = __shfl_sync(FULL, i1, 0);
        i2 = __shfl_sync(FULL, i2, 0);

        const float w0 = __fdiv_rn(1.0f, fmaxf(b0, 1e-16f));
        const float w1 = __fdiv_rn(1.0f, fmaxf(b1, 1e-16f));
        const float w2 = __fdiv_rn(1.0f, fmaxf(b2, 1e-16f));
        const float den = __fadd_rn(__fadd_rn(w0, w1), w2);

        const float* x0 = x + ((size_t)b * NSRC + i0) * CIN;
        const float* x1 = x + ((size_t)b * NSRC + i1) * CIN;
        const float* x2 = x + ((size_t)b * NSRC + i2) * CIN;
        __nv_bfloat16* xh = g_xin_hi + (size_t)m * CCAT;
        __nv_bfloat16* xl = g_xin_lo + (size_t)m * CCAT;

#pragma unroll
        for (int c = l; c < CIN; c += 32) {
            float num = __fadd_rn(__fadd_rn(__fmul_rn(w0, x0[c]),
                                            __fmul_rn(w1, x1[c])),
                                  __fmul_rn(w2, x2[c]));
            float v = __fdiv_rn(num, den);
            uint16_t h, lo;
            split_bf16(v, h, lo);
            xh[c] = __ushort_as_bfloat16(h);
            xl[c] = __ushort_as_bfloat16(lo);
        }
        const float* xs = x_skip + (size_t)m * CSKIP;
#pragma unroll
        for (int c = l; c < CSKIP; c += 32) {
            uint16_t h, lo;
            split_bf16(xs[c], h, lo);
            xh[CIN + c] = __ushort_as_bfloat16(h);
            xl[CIN + c] = __ushort_as_bfloat16(lo);
        }
    }
}

// ---------------------------------------------------------------------------
// WMMA split-bf16 GEMM:  C[M,N] = epi(A @ B^T + bias)
//   A planes [M, KTOT] bf16 hi/lo (K-major); B planes [N, KTOT] bf16 hi/lo.
//   Block tile 128x128, 8 warps, warp tile 32x64 (2x4 of 16x16 wmma frags).
//   3-term split: AhBh + AhBl + AlBh, fp32 accumulate.
//   EPI 0: +bias, relu, split-bf16 -> g_h1 planes.
//   EPI 1: +bias, *gate[batch], fp32 -> out.
// ---------------------------------------------------------------------------
#define BK_G   32
#define STRD   48                         // smem stride (elems): 96B, 32B-aligned
#define PLANE_ELEMS (128 * STRD)          // 6144 elems = 12288 B per plane
#define CSTR   72                         // epilogue C buffer stride (floats)

template<int N, int KTOT, int EPI>
__global__ __launch_bounds__(256)
void wmma_gemm_kernel(const __nv_bfloat16* __restrict__ Ah,
                      const __nv_bfloat16* __restrict__ Al,
                      const __nv_bfloat16* __restrict__ Bh,
                      const __nv_bfloat16* __restrict__ Bl,
                      const float* __restrict__ bias,
                      float* __restrict__ outp) {
    extern __shared__ char smem[];
    __nv_bfloat16* sAh = (__nv_bfloat16*)smem;
    __nv_bfloat16* sAl = sAh + PLANE_ELEMS;
    __nv_bfloat16* sBh = sAl + PLANE_ELEMS;
    __nv_bfloat16* sBl = sBh + PLANE_ELEMS;
    float* cbuf = (float*)smem;           // reused after mainloop

    const int tid  = threadIdx.x;
    const int w    = tid >> 5;
    const int lane = tid & 31;
    const int bm   = blockIdx.y * 128;
    const int bn   = blockIdx.x * 128;
    const int wm   = (w & 3) * 32;        // warp M offset in tile
    const int wn   = (w >> 2) * 64;       // warp N offset in tile

    wmma::fragment<wmma::accumulator, 16, 16, 16, float> acc[2][4];
#pragma unroll
    for (int i = 0; i < 2; ++i)
#pragma unroll
        for (int j = 0; j < 4; ++j)
            wmma::fill_fragment(acc[i][j], 0.0f);

    for (int kc = 0; kc < KTOT / BK_G; ++kc) {
        __syncthreads();                  // staging reuse guard
        // stage 4 planes of [128 x 32] bf16 : 2048 x 16B units
#pragma unroll
        for (int u = tid; u < 2048; u += 256) {
            const int plane = u >> 9;
            const int idx   = u & 511;
            const int row   = idx >> 2;
            const int c     = idx & 3;
            const __nv_bfloat16* gsrc;
            __nv_bfloat16* sdst;
            if (plane < 2) {
                const __nv_bfloat16* P = plane ? Al : Ah;
                gsrc = P + (size_t)(bm + row) * KTOT + kc * BK_G + c * 8;
                sdst = (plane ? sAl : sAh) + row * STRD + c * 8;
            } else {
                const __nv_bfloat16* P = (plane == 3) ? Bl : Bh;
                gsrc = P + (size_t)(bn + row) * KTOT + kc * BK_G + c * 8;
                sdst = ((plane == 3) ? sBl : sBh) + row * STRD + c * 8;
            }
            *(uint4*)sdst = *(const uint4*)gsrc;
        }
        __syncthreads();

#pragma unroll
        for (int kk = 0; kk < BK_G; kk += 16) {
            wmma::fragment<wmma::matrix_a, 16, 16, 16, __nv_bfloat16,
                           wmma::row_major> a_h[2], a_l[2];
            wmma::fragment<wmma::matrix_b, 16, 16, 16, __nv_bfloat16,
                           wmma::col_major> b_h[4], b_l[4];
#pragma unroll
            for (int i = 0; i < 2; ++i) {
                wmma::load_matrix_sync(a_h[i], sAh + (wm + i * 16) * STRD + kk, STRD);
                wmma::load_matrix_sync(a_l[i], sAl + (wm + i * 16) * STRD + kk, STRD);
            }
#pragma unroll
            for (int j = 0; j < 4; ++j) {
                wmma::load_matrix_sync(b_h[j], sBh + (wn + j * 16) * STRD + kk, STRD);
                wmma::load_matrix_sync(b_l[j], sBl + (wn + j * 16) * STRD + kk, STRD);
            }
#pragma unroll
            for (int i = 0; i < 2; ++i)
#pragma unroll
                for (int j = 0; j < 4; ++j) {
                    wmma::mma_sync(acc[i][j], a_h[i], b_h[j], acc[i][j]);
                    wmma::mma_sync(acc[i][j], a_h[i], b_l[j], acc[i][j]);
                    wmma::mma_sync(acc[i][j], a_l[i], b_h[j], acc[i][j]);
                }
        }
    }
    __syncthreads();                      // all reads of staging done

    // dump accumulators to per-warp shared region [32][CSTR]
    float* cw = cbuf + w * (32 * CSTR);
#pragma unroll
    for (int i = 0; i < 2; ++i)
#pragma unroll
        for (int j = 0; j < 4; ++j)
            wmma::store_matrix_sync(cw + i * 16 * CSTR + j * 16, acc[i][j],
                                    CSTR, wmma::mem_row_major);
    __syncwarp();

    // epilogue: lane = row within warp tile; 64 cols
    const int m = bm + wm + lane;
    const int ncol0 = bn + wn;
    if (EPI == 0) {
        uint32_t* dh = (uint32_t*)(g_h1_hi + (size_t)m * N + ncol0);
        uint32_t* dl = (uint32_t*)(g_h1_lo + (size_t)m * N + ncol0);
#pragma unroll
        for (int c = 0; c < 64; c += 2) {
            float v0 = fmaxf(cw[lane * CSTR + c]     + bias[ncol0 + c],     0.0f);
            float v1 = fmaxf(cw[lane * CSTR + c + 1] + bias[ncol0 + c + 1], 0.0f);
            uint16_t h0, l0, h1, l1;
            split_bf16(v0, h0, l0);
            split_bf16(v1, h1, l1);
            dh[c >> 1] = (uint32_t)h0 | ((uint32_t)h1 << 16);
            dl[c >> 1] = (uint32_t)l0 | ((uint32_t)l1 << 16);
        }
    } else {
        const int batch = m >> 13;
        const float* gt = g_gate + batch * COUT;
        float4* dst = (float4*)(outp + (size_t)m * N + ncol0);
#pragma unroll
        for (int c = 0; c < 64; c += 4) {
            float4 o;
            o.x = (cw[lane * CSTR + c]     + bias[ncol0 + c])     * gt[ncol0 + c];
            o.y = (cw[lane * CSTR + c + 1] + bias[ncol0 + c + 1]) * gt[ncol0 + c + 1];
            o.z = (cw[lane * CSTR + c + 2] + bias[ncol0 + c + 2]) * gt[ncol0 + c + 2];
            o.w = (cw[lane * CSTR + c + 3] + bias[ncol0 + c + 3]) * gt[ncol0 + c + 3];
            dst[c >> 2] = o;
        }
    }
}

// ---------------------------------------------------------------------------
// Tail: pos_skip and batch_skip into concatenated output
// ---------------------------------------------------------------------------
__global__ void tail_kernel(const float* __restrict__ pos_skip,
                            float* __restrict__ out, int mode, int out_size) {
    int i = blockIdx.x * 256 + threadIdx.x;
    if (i < POS_ELEMS && OUT_ELEMS + i < out_size)
        out[OUT_ELEMS + i] = pos_skip[i];
    if (i < MTOT) {
        if (mode == 1) {
            int o = OUT_ELEMS + POS_ELEMS + i;
            if (o < out_size) out[o] = (float)(i >> 13);
        } else if (mode == 2) {
            int o = OUT_ELEMS + POS_ELEMS + 2 * i;
            if (o + 1 < out_size)
                ((long long*)(out + OUT_ELEMS + POS_ELEMS))[i] = (long long)(i >> 13);
        }
    }
}

// ---------------------------------------------------------------------------
extern "C" void kernel_launch(void* const* d_in, const int* in_sizes, int n_in,
                              void* d_out, int out_size) {
    const float* par      = (const float*)d_in[0];
    const float* x        = (const float*)d_in[1];
    const float* pos      = (const float*)d_in[2];
    const float* x_skip   = (const float*)d_in[3];
    const float* pos_skip = (const float*)d_in[4];
    const float* W1       = (const float*)d_in[5];
    const float* b1       = (const float*)d_in[6];
    const float* W2       = (const float*)d_in[7];
    const float* b2       = (const float*)d_in[8];
    const float* Wp       = (const float*)d_in[9];
    const float* bp       = (const float*)d_in[10];
    float* out = (float*)d_out;

    __nv_bfloat16 *p_xh, *p_xl, *p_hh, *p_hl, *p_w1h, *p_w1l, *p_w2h, *p_w2l;
    cudaGetSymbolAddress((void**)&p_xh,  g_xin_hi);
    cudaGetSymbolAddress((void**)&p_xl,  g_xin_lo);
    cudaGetSymbolAddress((void**)&p_hh,  g_h1_hi);
    cudaGetSymbolAddress((void**)&p_hl,  g_h1_lo);
    cudaGetSymbolAddress((void**)&p_w1h, g_w1t_hi);
    cudaGetSymbolAddress((void**)&p_w1l, g_w1t_lo);
    cudaGetSymbolAddress((void**)&p_w2h, g_w2t_hi);
    cudaGetSymbolAddress((void**)&p_w2l, g_w2t_lo);

    // smem: max(staging 4*12288 = 49152, cbuf 8*32*72*4 = 73728)
    constexpr int SMEM_G = 73728;
    cudaFuncSetAttribute(wmma_gemm_kernel<HDIM, CCAT, 0>,
                         cudaFuncAttributeMaxDynamicSharedMemorySize, SMEM_G);
    cudaFuncSetAttribute(wmma_gemm_kernel<COUT, HDIM, 1>,
                         cudaFuncAttributeMaxDynamicSharedMemorySize, SMEM_G);

    gate_kernel<<<1, 512>>>(par, Wp, bp);
    prep_w_kernel<<<(CCAT * HDIM + 255) / 256, 256>>>(W1, W2);

    dim3 kg(BPB, NB);
    knn_interp_kernel<<<kg, 256>>>(x, pos, x_skip, pos_skip);

    dim3 g1(HDIM / 128, MTOT / 128);       // (2, 256)
    wmma_gemm_kernel<HDIM, CCAT, 0><<<g1, 256, SMEM_G>>>(
        p_xh, p_xl, p_w1h, p_w1l, b1, nullptr);

    dim3 g2(COUT / 128, MTOT / 128);       // (1, 256)
    wmma_gemm_kernel<COUT, HDIM, 1><<<g2, 256, SMEM_G>>>(
        p_hh, p_hl, p_w2h, p_w2l, b2, out);

    const int tail = out_size - OUT_ELEMS;
    if (tail > 0) {
        int mode = 0;
        if (tail >= POS_ELEMS + 2 * MTOT)      mode = 2;
        else if (tail >= POS_ELEMS + MTOT)     mode = 1;
        tail_kernel<<<(POS_ELEMS + 255) / 256, 256>>>(pos_skip, out, mode, out_size);
    }
}

// round 8
// speedup vs baseline: 1.1594x; 1.0864x over previous
#include <cuda_runtime.h>
#include <cuda_bf16.h>
#include <math_constants.h>
#include <cstdint>
#include <mma.h>

using namespace nvcuda;

#define NB     4
#define NSRC   2048
#define NDST   8192
#define CIN    256
#define CSKIP  128
#define CCAT   384
#define HDIM   256
#define COUT   128
#define PDIM   64
#define MTOT   (NB * NDST)          // 32768

#define OUT_ELEMS   (MTOT * COUT)   // 4194304
#define POS_ELEMS   (MTOT * 3)      // 98304

// ---------------------------------------------------------------------------
// Scratch (__device__ globals; no allocations allowed)
// ---------------------------------------------------------------------------
__device__ __nv_bfloat16 g_xin_hi[MTOT * CCAT];   // A1 hi plane, [M,K] K-major
__device__ __nv_bfloat16 g_xin_lo[MTOT * CCAT];
__device__ __nv_bfloat16 g_h1_hi[MTOT * HDIM];    // A2 hi plane
__device__ __nv_bfloat16 g_h1_lo[MTOT * HDIM];
__device__ __nv_bfloat16 g_w1t_hi[HDIM * CCAT];   // B1 [N=256, K=384]
__device__ __nv_bfloat16 g_w1t_lo[HDIM * CCAT];
__device__ __nv_bfloat16 g_w2t_hi[COUT * HDIM];   // B2 [N=128, K=256]
__device__ __nv_bfloat16 g_w2t_lo[COUT * HDIM];
__device__ float g_gate[NB * COUT];

// fp32 -> bf16 hi/lo split
__device__ __forceinline__ void split_bf16(float v, uint16_t& h, uint16_t& l) {
    __nv_bfloat16 hb = __float2bfloat16_rn(v);
    float r = v - __bfloat162float(hb);
    __nv_bfloat16 lb = __float2bfloat16_rn(r);
    h = __bfloat16_as_ushort(hb);
    l = __bfloat16_as_ushort(lb);
}

// cp.async helpers (sm_80 baseline — legal on sm_103 target)
__device__ __forceinline__ void cp_async16(uint32_t dst, const void* src) {
    asm volatile("cp.async.ca.shared.global [%0], [%1], 16;"
                 :: "r"(dst), "l"(src) : "memory");
}
#define CP_COMMIT() asm volatile("cp.async.commit_group;" ::: "memory")
#define CP_WAIT(n)  asm volatile("cp.async.wait_group %0;" :: "n"(n) : "memory")

// ---------------------------------------------------------------------------
// gate + weight prep fused
// ---------------------------------------------------------------------------
__global__ void prep_kernel(const float* __restrict__ par,
                            const float* __restrict__ Wp,
                            const float* __restrict__ bp,
                            const float* __restrict__ W1,
                            const float* __restrict__ W2) {
    int i = blockIdx.x * 256 + threadIdx.x;
    if (i < NB * COUT) {
        int b = i >> 7, n = i & 127;
        float acc = bp[n];
        const float* pe = par + b * PDIM;
#pragma unroll
        for (int p = 0; p < PDIM; ++p)
            acc = fmaf(pe[p], Wp[p * COUT + n], acc);
        g_gate[i] = fmaxf(acc, 0.0f);
    }
    if (i < CCAT * HDIM) {
        int k = i / HDIM, n = i % HDIM;
        uint16_t h, l;
        split_bf16(W1[i], h, l);
        g_w1t_hi[n * CCAT + k] = __ushort_as_bfloat16(h);
        g_w1t_lo[n * CCAT + k] = __ushort_as_bfloat16(l);
    }
    if (i < HDIM * COUT) {
        int k = i / COUT, n = i % COUT;
        uint16_t h, l;
        split_bf16(W2[i], h, l);
        g_w2t_hi[n * HDIM + k] = __ushort_as_bfloat16(h);
        g_w2t_lo[n * HDIM + k] = __ushort_as_bfloat16(l);
    }
}

// ---------------------------------------------------------------------------
// KNN (k=3) + inverse-squared-distance interpolate + concat x_skip.
// d2 rounding matches the reference bit-exactly (R5-validated).
// ---------------------------------------------------------------------------
__device__ __forceinline__ void insert3(float d, int j,
                                        float& b0, float& b1, float& b2,
                                        int& i0, int& i1, int& i2) {
    bool lt2 = (d < b2) || (d == b2 && j < i2);
    if (lt2) {
        bool lt1 = (d < b1) || (d == b1 && j < i1);
        if (lt1) {
            b2 = b1; i2 = i1;
            bool lt0 = (d < b0) || (d == b0 && j < i0);
            if (lt0) { b1 = b0; i1 = i0; b0 = d; i0 = j; }
            else     { b1 = d;  i1 = j; }
        } else { b2 = d; i2 = j; }
    }
}

#define BPB 64
#define DPB (NDST / BPB)

__global__ __launch_bounds__(256)
void knn_interp_kernel(const float* __restrict__ x,
                       const float* __restrict__ pos,
                       const float* __restrict__ x_skip,
                       const float* __restrict__ pos_skip) {
    __shared__ float sx[NSRC], sy[NSRC], sz[NSRC], s2[NSRC];
    const int b   = blockIdx.y;
    const int tid = threadIdx.x;

    const float* sp = pos + (size_t)b * NSRC * 3;
    for (int i = tid; i < NSRC; i += 256) {
        float px = sp[i * 3 + 0];
        float py = sp[i * 3 + 1];
        float pz = sp[i * 3 + 2];
        sx[i] = px; sy[i] = py; sz[i] = pz;
        s2[i] = __fmaf_rn(pz, pz, __fmaf_rn(py, py, __fmul_rn(px, px)));
    }
    __syncthreads();

    const int w = tid >> 5;
    const int l = tid & 31;
    const unsigned FULL = 0xffffffffu;

    for (int local = w; local < DPB; local += 8) {
        const int m = b * NDST + blockIdx.x * DPB + local;
        const float dx = pos_skip[m * 3 + 0];
        const float dy = pos_skip[m * 3 + 1];
        const float dz = pos_skip[m * 3 + 2];
        const float dd = __fmaf_rn(dz, dz, __fmaf_rn(dy, dy, __fmul_rn(dx, dx)));

        float b0 = CUDART_INF_F, b1 = CUDART_INF_F, b2 = CUDART_INF_F;
        int   i0 = 0x7fffffff, i1 = 0x7fffffff, i2 = 0x7fffffff;

        for (int j = l; j < NSRC; j += 32) {
            float dot = __fmaf_rn(dz, sz[j],
                        __fmaf_rn(dy, sy[j],
                        __fmul_rn(dx, sx[j])));
            float d2 = __fadd_rn(__fadd_rn(dd, s2[j]),
                                 -__fmul_rn(2.0f, dot));
            insert3(d2, j, b0, b1, b2, i0, i1, i2);
        }
        for (int off = 16; off; off >>= 1) {
            float c0 = __shfl_down_sync(FULL, b0, off);
            float c1 = __shfl_down_sync(FULL, b1, off);
            float c2 = __shfl_down_sync(FULL, b2, off);
            int   j0 = __shfl_down_sync(FULL, i0, off);
            int   j1 = __shfl_down_sync(FULL, i1, off);
            int   j2 = __shfl_down_sync(FULL, i2, off);
            insert3(c0, j0, b0, b1, b2, i0, i1, i2);
            insert3(c1, j1, b0, b1, b2, i0, i1, i2);
            insert3(c2, j2, b0, b1, b2, i0, i1, i2);
        }
        b0 = __shfl_sync(FULL, b0, 0);
        b1 = __shfl_sync(FULL, b1, 0);
        b2 = __shfl_sync(FULL, b2, 0);
        i0 = __shfl_sync(FULL, i0, 0);
        i1 = __shfl_sync(FULL, i1, 0);
        i2 = __shfl_sync(FULL, i2, 0);

        const float w0 = __fdiv_rn(1.0f, fmaxf(b0, 1e-16f));
        const float w1 = __fdiv_rn(1.0f, fmaxf(b1, 1e-16f));
        const float w2 = __fdiv_rn(1.0f, fmaxf(b2, 1e-16f));
        const float den = __fadd_rn(__fadd_rn(w0, w1), w2);

        const float* x0 = x + ((size_t)b * NSRC + i0) * CIN;
        const float* x1 = x + ((size_t)b * NSRC + i1) * CIN;
        const float* x2 = x + ((size_t)b * NSRC + i2) * CIN;
        __nv_bfloat16* xh = g_xin_hi + (size_t)m * CCAT;
        __nv_bfloat16* xl = g_xin_lo + (size_t)m * CCAT;

#pragma unroll
        for (int c = l; c < CIN; c += 32) {
            float num = __fadd_rn(__fadd_rn(__fmul_rn(w0, x0[c]),
                                            __fmul_rn(w1, x1[c])),
                                  __fmul_rn(w2, x2[c]));
            float v = __fdiv_rn(num, den);
            uint16_t h, lo;
            split_bf16(v, h, lo);
            xh[c] = __ushort_as_bfloat16(h);
            xl[c] = __ushort_as_bfloat16(lo);
        }
        const float* xs = x_skip + (size_t)m * CSKIP;
#pragma unroll
        for (int c = l; c < CSKIP; c += 32) {
            uint16_t h, lo;
            split_bf16(xs[c], h, lo);
            xh[CIN + c] = __ushort_as_bfloat16(h);
            xl[CIN + c] = __ushort_as_bfloat16(lo);
        }
    }
}

// ---------------------------------------------------------------------------
// WMMA split-bf16 GEMM:  C[M,N] = epi(A @ B^T + bias)
//   cp.async double-buffered staging, conflict-free 80B smem stride.
//   Block tile 128x128, 8 warps, warp tile 32x64.
//   3-term split: AhBh + AhBl + AlBh, fp32 accumulate.
// ---------------------------------------------------------------------------
#define BK_G   32
#define STRD   40                          // 80B row stride: conflict-free LDSM
#define PL_B   (128 * STRD * 2)            // plane bytes = 10240
#define BUF_B  (4 * PL_B)                  // 4 planes per buffer = 40960
#define CSTR   68                          // epilogue C buffer stride (floats)

template<int N, int KTOT, int EPI>
__global__ __launch_bounds__(256, 2)
void wmma_gemm_kernel(const __nv_bfloat16* __restrict__ Ah,
                      const __nv_bfloat16* __restrict__ Al,
                      const __nv_bfloat16* __restrict__ Bh,
                      const __nv_bfloat16* __restrict__ Bl,
                      const float* __restrict__ bias,
                      float* __restrict__ outp) {
    constexpr int NC = KTOT / BK_G;
    extern __shared__ char smem[];
    const uint32_t sbase = (uint32_t)__cvta_generic_to_shared(smem);

    const int tid  = threadIdx.x;
    const int w    = tid >> 5;
    const int lane = tid & 31;
    const int bm   = blockIdx.y * 128;
    const int bn   = blockIdx.x * 128;
    const int wm   = (w & 3) * 32;
    const int wn   = (w >> 2) * 64;

    // staging thread mapping: u in [0,2048): plane(2b) | row(7b) | c(2b)
    const int su_plane = tid >> 6;          // not used directly; per-u below

    auto stage = [&](int kc, int buf) {
#pragma unroll
        for (int u = tid; u < 2048; u += 256) {
            const int plane = u >> 9;
            const int idx   = u & 511;
            const int row   = idx >> 2;
            const int c     = idx & 3;
            const __nv_bfloat16* P =
                (plane == 0) ? Ah : (plane == 1) ? Al : (plane == 2) ? Bh : Bl;
            const int grow = (plane < 2) ? (bm + row) : (bn + row);
            const __nv_bfloat16* gsrc =
                P + (size_t)grow * KTOT + kc * BK_G + c * 8;
            uint32_t sdst = sbase + buf * BUF_B + plane * PL_B +
                            row * (STRD * 2) + c * 16;
            cp_async16(sdst, gsrc);
        }
    };
    (void)su_plane;

    wmma::fragment<wmma::accumulator, 16, 16, 16, float> acc[2][4];
#pragma unroll
    for (int i = 0; i < 2; ++i)
#pragma unroll
        for (int j = 0; j < 4; ++j)
            wmma::fill_fragment(acc[i][j], 0.0f);

    stage(0, 0);
    CP_COMMIT();

    for (int kc = 0; kc < NC; ++kc) {
        if (kc + 1 < NC) {
            stage(kc + 1, (kc + 1) & 1);
            CP_COMMIT();
            CP_WAIT(1);
        } else {
            CP_WAIT(0);
        }
        __syncthreads();

        const __nv_bfloat16* sb =
            (const __nv_bfloat16*)(smem + (kc & 1) * BUF_B);
        const __nv_bfloat16* sAh = sb;
        const __nv_bfloat16* sAl = sb + 128 * STRD;
        const __nv_bfloat16* sBh = sb + 2 * 128 * STRD;
        const __nv_bfloat16* sBl = sb + 3 * 128 * STRD;

#pragma unroll
        for (int kk = 0; kk < BK_G; kk += 16) {
            wmma::fragment<wmma::matrix_a, 16, 16, 16, __nv_bfloat16,
                           wmma::row_major> a_h[2], a_l[2];
#pragma unroll
            for (int i = 0; i < 2; ++i) {
                wmma::load_matrix_sync(a_h[i], sAh + (wm + i * 16) * STRD + kk, STRD);
                wmma::load_matrix_sync(a_l[i], sAl + (wm + i * 16) * STRD + kk, STRD);
            }
#pragma unroll
            for (int j = 0; j < 4; ++j) {
                wmma::fragment<wmma::matrix_b, 16, 16, 16, __nv_bfloat16,
                               wmma::col_major> b_h, b_l;
                wmma::load_matrix_sync(b_h, sBh + (wn + j * 16) * STRD + kk, STRD);
                wmma::load_matrix_sync(b_l, sBl + (wn + j * 16) * STRD + kk, STRD);
#pragma unroll
                for (int i = 0; i < 2; ++i) {
                    wmma::mma_sync(acc[i][j], a_h[i], b_h, acc[i][j]);
                    wmma::mma_sync(acc[i][j], a_h[i], b_l, acc[i][j]);
                    wmma::mma_sync(acc[i][j], a_l[i], b_h, acc[i][j]);
                }
            }
        }
        __syncthreads();
    }

    // epilogue: dump accumulators through per-warp shared slice
    float* cw = (float*)smem + w * (32 * CSTR);
#pragma unroll
    for (int i = 0; i < 2; ++i)
#pragma unroll
        for (int j = 0; j < 4; ++j)
            wmma::store_matrix_sync(cw + i * 16 * CSTR + j * 16, acc[i][j],
                                    CSTR, wmma::mem_row_major);
    __syncwarp();

    const int m = bm + wm + lane;
    const int ncol0 = bn + wn;
    if (EPI == 0) {
        uint32_t* dh = (uint32_t*)(g_h1_hi + (size_t)m * N + ncol0);
        uint32_t* dl = (uint32_t*)(g_h1_lo + (size_t)m * N + ncol0);
#pragma unroll
        for (int c = 0; c < 64; c += 2) {
            float v0 = fmaxf(cw[lane * CSTR + c]     + bias[ncol0 + c],     0.0f);
            float v1 = fmaxf(cw[lane * CSTR + c + 1] + bias[ncol0 + c + 1], 0.0f);
            uint16_t h0, l0, h1, l1;
            split_bf16(v0, h0, l0);
            split_bf16(v1, h1, l1);
            dh[c >> 1] = (uint32_t)h0 | ((uint32_t)h1 << 16);
            dl[c >> 1] = (uint32_t)l0 | ((uint32_t)l1 << 16);
        }
    } else {
        const int batch = m >> 13;
        const float* gt = g_gate + batch * COUT;
        float4* dst = (float4*)(outp + (size_t)m * N + ncol0);
#pragma unroll
        for (int c = 0; c < 64; c += 4) {
            float4 o;
            o.x = (cw[lane * CSTR + c]     + bias[ncol0 + c])     * gt[ncol0 + c];
            o.y = (cw[lane * CSTR + c + 1] + bias[ncol0 + c + 1]) * gt[ncol0 + c + 1];
            o.z = (cw[lane * CSTR + c + 2] + bias[ncol0 + c + 2]) * gt[ncol0 + c + 2];
            o.w = (cw[lane * CSTR + c + 3] + bias[ncol0 + c + 3]) * gt[ncol0 + c + 3];
            dst[c >> 2] = o;
        }
    }
}

// ---------------------------------------------------------------------------
// Tail: pos_skip and batch_skip into concatenated output
// ---------------------------------------------------------------------------
__global__ void tail_kernel(const float* __restrict__ pos_skip,
                            float* __restrict__ out, int mode, int out_size) {
    int i = blockIdx.x * 256 + threadIdx.x;
    if (i < POS_ELEMS && OUT_ELEMS + i < out_size)
        out[OUT_ELEMS + i] = pos_skip[i];
    if (i < MTOT) {
        if (mode == 1) {
            int o = OUT_ELEMS + POS_ELEMS + i;
            if (o < out_size) out[o] = (float)(i >> 13);
        } else if (mode == 2) {
            int o = OUT_ELEMS + POS_ELEMS + 2 * i;
            if (o + 1 < out_size)
                ((long long*)(out + OUT_ELEMS + POS_ELEMS))[i] = (long long)(i >> 13);
        }
    }
}

// ---------------------------------------------------------------------------
extern "C" void kernel_launch(void* const* d_in, const int* in_sizes, int n_in,
                              void* d_out, int out_size) {
    const float* par      = (const float*)d_in[0];
    const float* x        = (const float*)d_in[1];
    const float* pos      = (const float*)d_in[2];
    const float* x_skip   = (const float*)d_in[3];
    const float* pos_skip = (const float*)d_in[4];
    const float* W1       = (const float*)d_in[5];
    const float* b1       = (const float*)d_in[6];
    const float* W2       = (const float*)d_in[7];
    const float* b2       = (const float*)d_in[8];
    const float* Wp       = (const float*)d_in[9];
    const float* bp       = (const float*)d_in[10];
    float* out = (float*)d_out;

    __nv_bfloat16 *p_xh, *p_xl, *p_hh, *p_hl, *p_w1h, *p_w1l, *p_w2h, *p_w2l;
    cudaGetSymbolAddress((void**)&p_xh,  g_xin_hi);
    cudaGetSymbolAddress((void**)&p_xl,  g_xin_lo);
    cudaGetSymbolAddress((void**)&p_hh,  g_h1_hi);
    cudaGetSymbolAddress((void**)&p_hl,  g_h1_lo);
    cudaGetSymbolAddress((void**)&p_w1h, g_w1t_hi);
    cudaGetSymbolAddress((void**)&p_w1l, g_w1t_lo);
    cudaGetSymbolAddress((void**)&p_w2h, g_w2t_hi);
    cudaGetSymbolAddress((void**)&p_w2l, g_w2t_lo);

    // smem: max(2 staging buffers 81920, cbuf 8*32*68*4 = 69632) = 81920
    constexpr int SMEM_G = 2 * BUF_B;
    cudaFuncSetAttribute(wmma_gemm_kernel<HDIM, CCAT, 0>,
                         cudaFuncAttributeMaxDynamicSharedMemorySize, SMEM_G);
    cudaFuncSetAttribute(wmma_gemm_kernel<COUT, HDIM, 1>,
                         cudaFuncAttributeMaxDynamicSharedMemorySize, SMEM_G);

    prep_kernel<<<(CCAT * HDIM + 255) / 256, 256>>>(par, Wp, bp, W1, W2);

    dim3 kg(BPB, NB);
    knn_interp_kernel<<<kg, 256>>>(x, pos, x_skip, pos_skip);

    dim3 g1(HDIM / 128, MTOT / 128);       // (2, 256)
    wmma_gemm_kernel<HDIM, CCAT, 0><<<g1, 256, SMEM_G>>>(
        p_xh, p_xl, p_w1h, p_w1l, b1, nullptr);

    dim3 g2(COUT / 128, MTOT / 128);       // (1, 256)
    wmma_gemm_kernel<COUT, HDIM, 1><<<g2, 256, SMEM_G>>>(
        p_hh, p_hl, p_w2h, p_w2l, b2, out);

    const int tail = out_size - OUT_ELEMS;
    if (tail > 0) {
        int mode = 0;
        if (tail >= POS_ELEMS + 2 * MTOT)      mode = 2;
        else if (tail >= POS_ELEMS + MTOT)     mode = 1;
        tail_kernel<<<(POS_ELEMS + 255) / 256, 256>>>(pos_skip, out, mode, out_size);
    }
}

// round 9
// speedup vs baseline: 1.4647x; 1.2634x over previous
#include <cuda_runtime.h>
#include <cuda_bf16.h>
#include <math_constants.h>
#include <cstdint>
#include <mma.h>

using namespace nvcuda;

#define NB     4
#define NSRC   2048
#define NDST   8192
#define CIN    256
#define CSKIP  128
#define CCAT   384
#define HDIM   256
#define COUT   128
#define PDIM   64
#define MTOT   (NB * NDST)          // 32768

#define OUT_ELEMS   (MTOT * COUT)   // 4194304
#define POS_ELEMS   (MTOT * 3)      // 98304

// ---------------------------------------------------------------------------
// Scratch (__device__ globals; no allocations allowed)
// ---------------------------------------------------------------------------
__device__ __nv_bfloat16 g_xin_hi[MTOT * CCAT];   // A1 hi plane, [M,K] K-major
__device__ __nv_bfloat16 g_xin_lo[MTOT * CCAT];
__device__ __nv_bfloat16 g_h1_hi[MTOT * HDIM];    // A2 hi plane
__device__ __nv_bfloat16 g_h1_lo[MTOT * HDIM];
__device__ __nv_bfloat16 g_w1t_hi[HDIM * CCAT];   // B1 [N=256, K=384]
__device__ __nv_bfloat16 g_w1t_lo[HDIM * CCAT];
__device__ __nv_bfloat16 g_w2t_hi[COUT * HDIM];   // B2 [N=128, K=256]
__device__ __nv_bfloat16 g_w2t_lo[COUT * HDIM];
__device__ float g_gate[NB * COUT];

// fp32 -> bf16 hi/lo split
__device__ __forceinline__ void split_bf16(float v, uint16_t& h, uint16_t& l) {
    __nv_bfloat16 hb = __float2bfloat16_rn(v);
    float r = v - __bfloat162float(hb);
    __nv_bfloat16 lb = __float2bfloat16_rn(r);
    h = __bfloat16_as_ushort(hb);
    l = __bfloat16_as_ushort(lb);
}

// cp.async helpers (sm_80 baseline — legal on sm_103 target)
__device__ __forceinline__ void cp_async16(uint32_t dst, const void* src) {
    asm volatile("cp.async.ca.shared.global [%0], [%1], 16;"
                 :: "r"(dst), "l"(src) : "memory");
}
#define CP_COMMIT() asm volatile("cp.async.commit_group;" ::: "memory")
#define CP_WAIT(n)  asm volatile("cp.async.wait_group %0;" :: "n"(n) : "memory")

// ---------------------------------------------------------------------------
// gate + weight prep fused
// ---------------------------------------------------------------------------
__global__ void prep_kernel(const float* __restrict__ par,
                            const float* __restrict__ Wp,
                            const float* __restrict__ bp,
                            const float* __restrict__ W1,
                            const float* __restrict__ W2) {
    int i = blockIdx.x * 256 + threadIdx.x;
    if (i < NB * COUT) {
        int b = i >> 7, n = i & 127;
        float acc = bp[n];
        const float* pe = par + b * PDIM;
#pragma unroll
        for (int p = 0; p < PDIM; ++p)
            acc = fmaf(pe[p], Wp[p * COUT + n], acc);
        g_gate[i] = fmaxf(acc, 0.0f);
    }
    if (i < CCAT * HDIM) {
        int k = i / HDIM, n = i % HDIM;
        uint16_t h, l;
        split_bf16(W1[i], h, l);
        g_w1t_hi[n * CCAT + k] = __ushort_as_bfloat16(h);
        g_w1t_lo[n * CCAT + k] = __ushort_as_bfloat16(l);
    }
    if (i < HDIM * COUT) {
        int k = i / COUT, n = i % COUT;
        uint16_t h, l;
        split_bf16(W2[i], h, l);
        g_w2t_hi[n * HDIM + k] = __ushort_as_bfloat16(h);
        g_w2t_lo[n * HDIM + k] = __ushort_as_bfloat16(l);
    }
}

// ---------------------------------------------------------------------------
// KNN (k=3) + inverse-squared-distance interpolate + concat x_skip.
//
// THREAD-PER-POINT branchless scan (no divergence, broadcast LDS.128):
//   d2 rounding matches the reference bit-exactly (R5-validated):
//     s2  = fma(z,z, fma(y,y, rn(x*x)))
//     dot = fma(dz,sz, fma(dy,sy, rn(dx*sx)))
//     d2  = rn( rn(dd + s2) - rn(2*dot) )
//   Sequential ascending-j scan with strict < == stable lowest-index
//   tie-break (jax.lax.top_k semantics). No merge phase needed.
// Interpolation + bf16 split write is warp-cooperative (coalesced).
// ---------------------------------------------------------------------------
#define PTS_PER_BLK 256

__global__ __launch_bounds__(256)
void knn_interp_kernel(const float* __restrict__ x,
                       const float* __restrict__ pos,
                       const float* __restrict__ x_skip,
                       const float* __restrict__ pos_skip) {
    __shared__ float4 spos[NSRC];                 // (x, y, z, s2)  32 KB
    __shared__ int   sI[3][PTS_PER_BLK];          // selected indices
    __shared__ float sW[4][PTS_PER_BLK];          // w0, w1, w2, den

    const int b   = blockIdx.y;
    const int tid = threadIdx.x;

    // stage candidate positions + exact s2
    const float* sp = pos + (size_t)b * NSRC * 3;
    for (int i = tid; i < NSRC; i += 256) {
        float px = sp[i * 3 + 0];
        float py = sp[i * 3 + 1];
        float pz = sp[i * 3 + 2];
        float s2 = __fmaf_rn(pz, pz, __fmaf_rn(py, py, __fmul_rn(px, px)));
        spos[i] = make_float4(px, py, pz, s2);
    }
    __syncthreads();

    // ---- per-thread scan: this thread owns one dst point ----
    const int pt = blockIdx.x * PTS_PER_BLK + tid;      // within batch
    const int m  = b * NDST + pt;                       // global dst row
    const float dx = pos_skip[m * 3 + 0];
    const float dy = pos_skip[m * 3 + 1];
    const float dz = pos_skip[m * 3 + 2];
    const float dd = __fmaf_rn(dz, dz, __fmaf_rn(dy, dy, __fmul_rn(dx, dx)));

    float b0 = CUDART_INF_F, b1 = CUDART_INF_F, b2 = CUDART_INF_F;
    int   i0 = 0, i1 = 0, i2 = 0;

#pragma unroll 4
    for (int j = 0; j < NSRC; ++j) {
        float4 c = spos[j];                              // broadcast LDS.128
        float dot = __fmaf_rn(dz, c.z,
                    __fmaf_rn(dy, c.y,
                    __fmul_rn(dx, c.x)));
        float d2 = __fadd_rn(__fadd_rn(dd, c.w),
                             -__fmul_rn(2.0f, dot));
        // branchless sorted insert, strict < (stable: later equal loses)
        bool p0 = d2 < b0;
        bool p1 = d2 < b1;
        bool p2 = d2 < b2;
        i2 = p1 ? i1 : (p2 ? j  : i2);
        b2 = p1 ? b1 : (p2 ? d2 : b2);
        i1 = p0 ? i0 : (p1 ? j  : i1);
        b1 = p0 ? b0 : (p1 ? d2 : b1);
        i0 = p0 ? j  : i0;
        b0 = p0 ? d2 : b0;
    }

    // weights exactly as reference: w = 1/max(d2,1e-16); den = (w0+w1)+w2
    {
        float w0 = __fdiv_rn(1.0f, fmaxf(b0, 1e-16f));
        float w1 = __fdiv_rn(1.0f, fmaxf(b1, 1e-16f));
        float w2 = __fdiv_rn(1.0f, fmaxf(b2, 1e-16f));
        sI[0][tid] = i0; sI[1][tid] = i1; sI[2][tid] = i2;
        sW[0][tid] = w0; sW[1][tid] = w1; sW[2][tid] = w2;
        sW[3][tid] = __fadd_rn(__fadd_rn(w0, w1), w2);
    }
    __syncthreads();

    // ---- warp-cooperative interpolation + split-bf16 write ----
    const int w    = tid >> 5;
    const int lane = tid & 31;
    for (int p = 0; p < 32; ++p) {
        const int slot = w * 32 + p;
        const int mm   = b * NDST + blockIdx.x * PTS_PER_BLK + slot;
        const int j0 = sI[0][slot], j1 = sI[1][slot], j2 = sI[2][slot];
        const float w0 = sW[0][slot], w1 = sW[1][slot], w2 = sW[2][slot];
        const float den = sW[3][slot];

        const float* x0 = x + ((size_t)b * NSRC + j0) * CIN;
        const float* x1 = x + ((size_t)b * NSRC + j1) * CIN;
        const float* x2 = x + ((size_t)b * NSRC + j2) * CIN;
        __nv_bfloat16* xh = g_xin_hi + (size_t)mm * CCAT;
        __nv_bfloat16* xl = g_xin_lo + (size_t)mm * CCAT;

#pragma unroll
        for (int c = lane; c < CIN; c += 32) {
            float num = __fadd_rn(__fadd_rn(__fmul_rn(w0, x0[c]),
                                            __fmul_rn(w1, x1[c])),
                                  __fmul_rn(w2, x2[c]));
            float v = __fdiv_rn(num, den);
            uint16_t h, lo;
            split_bf16(v, h, lo);
            xh[c] = __ushort_as_bfloat16(h);
            xl[c] = __ushort_as_bfloat16(lo);
        }
        const float* xs = x_skip + (size_t)mm * CSKIP;
#pragma unroll
        for (int c = lane; c < CSKIP; c += 32) {
            uint16_t h, lo;
            split_bf16(xs[c], h, lo);
            xh[CIN + c] = __ushort_as_bfloat16(h);
            xl[CIN + c] = __ushort_as_bfloat16(lo);
        }
    }
}

// ---------------------------------------------------------------------------
// WMMA split-bf16 GEMM:  C[M,N] = epi(A @ B^T + bias)
//   cp.async double-buffered staging, conflict-free 80B smem stride.
//   Block tile 128x128, 8 warps, warp tile 32x64.
//   3-term split: AhBh + AhBl + AlBh, fp32 accumulate.
// ---------------------------------------------------------------------------
#define BK_G   32
#define STRD   40                          // 80B row stride: conflict-free LDSM
#define PL_B   (128 * STRD * 2)            // plane bytes = 10240
#define BUF_B  (4 * PL_B)                  // 4 planes per buffer = 40960
#define CSTR   68                          // epilogue C buffer stride (floats)

template<int N, int KTOT, int EPI>
__global__ __launch_bounds__(256, 2)
void wmma_gemm_kernel(const __nv_bfloat16* __restrict__ Ah,
                      const __nv_bfloat16* __restrict__ Al,
                      const __nv_bfloat16* __restrict__ Bh,
                      const __nv_bfloat16* __restrict__ Bl,
                      const float* __restrict__ bias,
                      float* __restrict__ outp) {
    constexpr int NC = KTOT / BK_G;
    extern __shared__ char smem[];
    const uint32_t sbase = (uint32_t)__cvta_generic_to_shared(smem);

    const int tid  = threadIdx.x;
    const int w    = tid >> 5;
    const int lane = tid & 31;
    const int bm   = blockIdx.y * 128;
    const int bn   = blockIdx.x * 128;
    const int wm   = (w & 3) * 32;
    const int wn   = (w >> 2) * 64;

    auto stage = [&](int kc, int buf) {
#pragma unroll
        for (int u = tid; u < 2048; u += 256) {
            const int plane = u >> 9;
            const int idx   = u & 511;
            const int row   = idx >> 2;
            const int c     = idx & 3;
            const __nv_bfloat16* P =
                (plane == 0) ? Ah : (plane == 1) ? Al : (plane == 2) ? Bh : Bl;
            const int grow = (plane < 2) ? (bm + row) : (bn + row);
            const __nv_bfloat16* gsrc =
                P + (size_t)grow * KTOT + kc * BK_G + c * 8;
            uint32_t sdst = sbase + buf * BUF_B + plane * PL_B +
                            row * (STRD * 2) + c * 16;
            cp_async16(sdst, gsrc);
        }
    };

    wmma::fragment<wmma::accumulator, 16, 16, 16, float> acc[2][4];
#pragma unroll
    for (int i = 0; i < 2; ++i)
#pragma unroll
        for (int j = 0; j < 4; ++j)
            wmma::fill_fragment(acc[i][j], 0.0f);

    stage(0, 0);
    CP_COMMIT();

    for (int kc = 0; kc < NC; ++kc) {
        if (kc + 1 < NC) {
            stage(kc + 1, (kc + 1) & 1);
            CP_COMMIT();
            CP_WAIT(1);
        } else {
            CP_WAIT(0);
        }
        __syncthreads();

        const __nv_bfloat16* sb =
            (const __nv_bfloat16*)(smem + (kc & 1) * BUF_B);
        const __nv_bfloat16* sAh = sb;
        const __nv_bfloat16* sAl = sb + 128 * STRD;
        const __nv_bfloat16* sBh = sb + 2 * 128 * STRD;
        const __nv_bfloat16* sBl = sb + 3 * 128 * STRD;

#pragma unroll
        for (int kk = 0; kk < BK_G; kk += 16) {
            wmma::fragment<wmma::matrix_a, 16, 16, 16, __nv_bfloat16,
                           wmma::row_major> a_h[2], a_l[2];
#pragma unroll
            for (int i = 0; i < 2; ++i) {
                wmma::load_matrix_sync(a_h[i], sAh + (wm + i * 16) * STRD + kk, STRD);
                wmma::load_matrix_sync(a_l[i], sAl + (wm + i * 16) * STRD + kk, STRD);
            }
#pragma unroll
            for (int j = 0; j < 4; ++j) {
                wmma::fragment<wmma::matrix_b, 16, 16, 16, __nv_bfloat16,
                               wmma::col_major> b_h, b_l;
                wmma::load_matrix_sync(b_h, sBh + (wn + j * 16) * STRD + kk, STRD);
                wmma::load_matrix_sync(b_l, sBl + (wn + j * 16) * STRD + kk, STRD);
#pragma unroll
                for (int i = 0; i < 2; ++i) {
                    wmma::mma_sync(acc[i][j], a_h[i], b_h, acc[i][j]);
                    wmma::mma_sync(acc[i][j], a_h[i], b_l, acc[i][j]);
                    wmma::mma_sync(acc[i][j], a_l[i], b_h, acc[i][j]);
                }
            }
        }
        __syncthreads();
    }

    // epilogue: dump accumulators through per-warp shared slice
    float* cw = (float*)smem + w * (32 * CSTR);
#pragma unroll
    for (int i = 0; i < 2; ++i)
#pragma unroll
        for (int j = 0; j < 4; ++j)
            wmma::store_matrix_sync(cw + i * 16 * CSTR + j * 16, acc[i][j],
                                    CSTR, wmma::mem_row_major);
    __syncwarp();

    const int m = bm + wm + lane;
    const int ncol0 = bn + wn;
    if (EPI == 0) {
        uint32_t* dh = (uint32_t*)(g_h1_hi + (size_t)m * N + ncol0);
        uint32_t* dl = (uint32_t*)(g_h1_lo + (size_t)m * N + ncol0);
#pragma unroll
        for (int c = 0; c < 64; c += 2) {
            float v0 = fmaxf(cw[lane * CSTR + c]     + bias[ncol0 + c],     0.0f);
            float v1 = fmaxf(cw[lane * CSTR + c + 1] + bias[ncol0 + c + 1], 0.0f);
            uint16_t h0, l0, h1, l1;
            split_bf16(v0, h0, l0);
            split_bf16(v1, h1, l1);
            dh[c >> 1] = (uint32_t)h0 | ((uint32_t)h1 << 16);
            dl[c >> 1] = (uint32_t)l0 | ((uint32_t)l1 << 16);
        }
    } else {
        const int batch = m >> 13;
        const float* gt = g_gate + batch * COUT;
        float4* dst = (float4*)(outp + (size_t)m * N + ncol0);
#pragma unroll
        for (int c = 0; c < 64; c += 4) {
            float4 o;
            o.x = (cw[lane * CSTR + c]     + bias[ncol0 + c])     * gt[ncol0 + c];
            o.y = (cw[lane * CSTR + c + 1] + bias[ncol0 + c + 1]) * gt[ncol0 + c + 1];
            o.z = (cw[lane * CSTR + c + 2] + bias[ncol0 + c + 2]) * gt[ncol0 + c + 2];
            o.w = (cw[lane * CSTR + c + 3] + bias[ncol0 + c + 3]) * gt[ncol0 + c + 3];
            dst[c >> 2] = o;
        }
    }
}

// ---------------------------------------------------------------------------
// Tail: pos_skip and batch_skip into concatenated output
// ---------------------------------------------------------------------------
__global__ void tail_kernel(const float* __restrict__ pos_skip,
                            float* __restrict__ out, int mode, int out_size) {
    int i = blockIdx.x * 256 + threadIdx.x;
    if (i < POS_ELEMS && OUT_ELEMS + i < out_size)
        out[OUT_ELEMS + i] = pos_skip[i];
    if (i < MTOT) {
        if (mode == 1) {
            int o = OUT_ELEMS + POS_ELEMS + i;
            if (o < out_size) out[o] = (float)(i >> 13);
        } else if (mode == 2) {
            int o = OUT_ELEMS + POS_ELEMS + 2 * i;
            if (o + 1 < out_size)
                ((long long*)(out + OUT_ELEMS + POS_ELEMS))[i] = (long long)(i >> 13);
        }
    }
}

// ---------------------------------------------------------------------------
extern "C" void kernel_launch(void* const* d_in, const int* in_sizes, int n_in,
                              void* d_out, int out_size) {
    const float* par      = (const float*)d_in[0];
    const float* x        = (const float*)d_in[1];
    const float* pos      = (const float*)d_in[2];
    const float* x_skip   = (const float*)d_in[3];
    const float* pos_skip = (const float*)d_in[4];
    const float* W1       = (const float*)d_in[5];
    const float* b1       = (const float*)d_in[6];
    const float* W2       = (const float*)d_in[7];
    const float* b2       = (const float*)d_in[8];
    const float* Wp       = (const float*)d_in[9];
    const float* bp       = (const float*)d_in[10];
    float* out = (float*)d_out;

    __nv_bfloat16 *p_xh, *p_xl, *p_hh, *p_hl, *p_w1h, *p_w1l, *p_w2h, *p_w2l;
    cudaGetSymbolAddress((void**)&p_xh,  g_xin_hi);
    cudaGetSymbolAddress((void**)&p_xl,  g_xin_lo);
    cudaGetSymbolAddress((void**)&p_hh,  g_h1_hi);
    cudaGetSymbolAddress((void**)&p_hl,  g_h1_lo);
    cudaGetSymbolAddress((void**)&p_w1h, g_w1t_hi);
    cudaGetSymbolAddress((void**)&p_w1l, g_w1t_lo);
    cudaGetSymbolAddress((void**)&p_w2h, g_w2t_hi);
    cudaGetSymbolAddress((void**)&p_w2l, g_w2t_lo);

    constexpr int SMEM_G = 2 * BUF_B;   // 81920
    cudaFuncSetAttribute(wmma_gemm_kernel<HDIM, CCAT, 0>,
                         cudaFuncAttributeMaxDynamicSharedMemorySize, SMEM_G);
    cudaFuncSetAttribute(wmma_gemm_kernel<COUT, HDIM, 1>,
                         cudaFuncAttributeMaxDynamicSharedMemorySize, SMEM_G);

    prep_kernel<<<(CCAT * HDIM + 255) / 256, 256>>>(par, Wp, bp, W1, W2);

    dim3 kg(NDST / PTS_PER_BLK, NB);       // (32, 4)
    knn_interp_kernel<<<kg, 256>>>(x, pos, x_skip, pos_skip);

    dim3 g1(HDIM / 128, MTOT / 128);       // (2, 256)
    wmma_gemm_kernel<HDIM, CCAT, 0><<<g1, 256, SMEM_G>>>(
        p_xh, p_xl, p_w1h, p_w1l, b1, nullptr);

    dim3 g2(COUT / 128, MTOT / 128);       // (1, 256)
    wmma_gemm_kernel<COUT, HDIM, 1><<<g2, 256, SMEM_G>>>(
        p_hh, p_hl, p_w2h, p_w2l, b2, out);

    const int tail = out_size - OUT_ELEMS;
    if (tail > 0) {
        int mode = 0;
        if (tail >= POS_ELEMS + 2 * MTOT)      mode = 2;
        else if (tail >= POS_ELEMS + MTOT)     mode = 1;
        tail_kernel<<<(POS_ELEMS + 255) / 256, 256>>>(pos_skip, out, mode, out_size);
    }
}

// round 10
// speedup vs baseline: 1.8317x; 1.2505x over previous
#include <cuda_runtime.h>
#include <cuda_bf16.h>
#include <math_constants.h>
#include <cstdint>
#include <mma.h>

using namespace nvcuda;

#define NB     4
#define NSRC   2048
#define NDST   8192
#define CIN    256
#define CSKIP  128
#define CCAT   384
#define HDIM   256
#define COUT   128
#define PDIM   64
#define MTOT   (NB * NDST)          // 32768

#define OUT_ELEMS   (MTOT * COUT)   // 4194304
#define POS_ELEMS   (MTOT * 3)      // 98304

// ---------------------------------------------------------------------------
// Scratch (__device__ globals; no allocations allowed)
// ---------------------------------------------------------------------------
__device__ __nv_bfloat16 g_xin_hi[MTOT * CCAT];   // A1 hi plane, [M,K] K-major
__device__ __nv_bfloat16 g_xin_lo[MTOT * CCAT];
__device__ __nv_bfloat16 g_h1_hi[MTOT * HDIM];    // A2 hi plane
__device__ __nv_bfloat16 g_h1_lo[MTOT * HDIM];
__device__ __nv_bfloat16 g_w1t_hi[HDIM * CCAT];   // B1 [N=256, K=384]
__device__ __nv_bfloat16 g_w1t_lo[HDIM * CCAT];
__device__ __nv_bfloat16 g_w2t_hi[COUT * HDIM];   // B2 [N=128, K=256]
__device__ __nv_bfloat16 g_w2t_lo[COUT * HDIM];
__device__ float g_gate[NB * COUT];

// fp32 -> bf16 hi/lo split
__device__ __forceinline__ void split_bf16(float v, uint16_t& h, uint16_t& l) {
    __nv_bfloat16 hb = __float2bfloat16_rn(v);
    float r = v - __bfloat162float(hb);
    __nv_bfloat16 lb = __float2bfloat16_rn(r);
    h = __bfloat16_as_ushort(hb);
    l = __bfloat16_as_ushort(lb);
}

// cp.async helpers (sm_80 baseline — legal on sm_103 target)
__device__ __forceinline__ void cp_async16(uint32_t dst, const void* src) {
    asm volatile("cp.async.ca.shared.global [%0], [%1], 16;"
                 :: "r"(dst), "l"(src) : "memory");
}
#define CP_COMMIT() asm volatile("cp.async.commit_group;" ::: "memory")
#define CP_WAIT(n)  asm volatile("cp.async.wait_group %0;" :: "n"(n) : "memory")

// ---------------------------------------------------------------------------
// gate + weight prep fused
// ---------------------------------------------------------------------------
__global__ void prep_kernel(const float* __restrict__ par,
                            const float* __restrict__ Wp,
                            const float* __restrict__ bp,
                            const float* __restrict__ W1,
                            const float* __restrict__ W2) {
    int i = blockIdx.x * 256 + threadIdx.x;
    if (i < NB * COUT) {
        int b = i >> 7, n = i & 127;
        float acc = bp[n];
        const float* pe = par + b * PDIM;
#pragma unroll
        for (int p = 0; p < PDIM; ++p)
            acc = fmaf(pe[p], Wp[p * COUT + n], acc);
        g_gate[i] = fmaxf(acc, 0.0f);
    }
    if (i < CCAT * HDIM) {
        int k = i / HDIM, n = i % HDIM;
        uint16_t h, l;
        split_bf16(W1[i], h, l);
        g_w1t_hi[n * CCAT + k] = __ushort_as_bfloat16(h);
        g_w1t_lo[n * CCAT + k] = __ushort_as_bfloat16(l);
    }
    if (i < HDIM * COUT) {
        int k = i / COUT, n = i % COUT;
        uint16_t h, l;
        split_bf16(W2[i], h, l);
        g_w2t_hi[n * HDIM + k] = __ushort_as_bfloat16(h);
        g_w2t_lo[n * HDIM + k] = __ushort_as_bfloat16(l);
    }
}

// ---------------------------------------------------------------------------
// KNN (k=3) + inverse-squared-distance interpolate + concat x_skip.
//
// Thread-per-point, TWO independent even/odd top-3 chains (halves the
// loop-carried FSETP->FSEL latency), merged with an index tie-break that
// reproduces sequential-stable (lowest index first) semantics exactly.
// d2 rounding matches the reference bit-exactly (R5-validated):
//   s2  = fma(z,z, fma(y,y, rn(x*x)))
//   dot = fma(dz,sz, fma(dy,sy, rn(dx*sx)))
//   d2  = rn( rn(dd + s2) - rn(2*dot) )
// Interpolation: float4 gathers, division hoisted to 1/den per point.
// ---------------------------------------------------------------------------
#define PTS_PER_BLK 256

__global__ __launch_bounds__(256)
void knn_interp_kernel(const float* __restrict__ x,
                       const float* __restrict__ pos,
                       const float* __restrict__ x_skip,
                       const float* __restrict__ pos_skip) {
    __shared__ float4 spos[NSRC];                 // (x, y, z, s2)  32 KB
    __shared__ int   sI[3][PTS_PER_BLK];
    __shared__ float sW[4][PTS_PER_BLK];          // w0, w1, w2, inv_den

    const int b   = blockIdx.y;
    const int tid = threadIdx.x;

    const float* sp = pos + (size_t)b * NSRC * 3;
    for (int i = tid; i < NSRC; i += 256) {
        float px = sp[i * 3 + 0];
        float py = sp[i * 3 + 1];
        float pz = sp[i * 3 + 2];
        float s2 = __fmaf_rn(pz, pz, __fmaf_rn(py, py, __fmul_rn(px, px)));
        spos[i] = make_float4(px, py, pz, s2);
    }
    __syncthreads();

    const int pt = blockIdx.x * PTS_PER_BLK + tid;
    const int m  = b * NDST + pt;
    const float dx = pos_skip[m * 3 + 0];
    const float dy = pos_skip[m * 3 + 1];
    const float dz = pos_skip[m * 3 + 2];
    const float dd = __fmaf_rn(dz, dz, __fmaf_rn(dy, dy, __fmul_rn(dx, dx)));

    // even-j chain (E) and odd-j chain (O)
    float ea0 = CUDART_INF_F, ea1 = CUDART_INF_F, ea2 = CUDART_INF_F;
    int   ei0 = 0, ei1 = 0, ei2 = 0;
    float oa0 = CUDART_INF_F, oa1 = CUDART_INF_F, oa2 = CUDART_INF_F;
    int   oi0 = 0, oi1 = 0, oi2 = 0;

#pragma unroll 2
    for (int j = 0; j < NSRC; j += 2) {
        float4 ce = spos[j];
        float4 co = spos[j + 1];
        float de = __fadd_rn(__fadd_rn(dd, ce.w),
                   -__fmul_rn(2.0f,
                    __fmaf_rn(dz, ce.z, __fmaf_rn(dy, ce.y, __fmul_rn(dx, ce.x)))));
        float dox = __fadd_rn(__fadd_rn(dd, co.w),
                    -__fmul_rn(2.0f,
                     __fmaf_rn(dz, co.z, __fmaf_rn(dy, co.y, __fmul_rn(dx, co.x)))));
        {   // E insert, strict < (scan-order stable)
            bool p0 = de < ea0, p1 = de < ea1, p2 = de < ea2;
            ei2 = p1 ? ei1 : (p2 ? j  : ei2);
            ea2 = p1 ? ea1 : (p2 ? de : ea2);
            ei1 = p0 ? ei0 : (p1 ? j  : ei1);
            ea1 = p0 ? ea0 : (p1 ? de : ea1);
            ei0 = p0 ? j   : ei0;
            ea0 = p0 ? de  : ea0;
        }
        {   // O insert
            bool p0 = dox < oa0, p1 = dox < oa1, p2 = dox < oa2;
            oi2 = p1 ? oi1 : (p2 ? j + 1 : oi2);
            oa2 = p1 ? oa1 : (p2 ? dox   : oa2);
            oi1 = p0 ? oi0 : (p1 ? j + 1 : oi1);
            oa1 = p0 ? oa0 : (p1 ? dox   : oa1);
            oi0 = p0 ? j + 1 : oi0;
            oa0 = p0 ? dox   : oa0;
        }
    }

    // merge O into E with lowest-index tie-break (exact stable semantics)
#pragma unroll
    for (int t = 0; t < 3; ++t) {
        float d  = (t == 0) ? oa0 : (t == 1) ? oa1 : oa2;
        int   jj = (t == 0) ? oi0 : (t == 1) ? oi1 : oi2;
        bool lt0 = (d < ea0) || (d == ea0 && jj < ei0);
        bool lt1 = (d < ea1) || (d == ea1 && jj < ei1);
        bool lt2 = (d < ea2) || (d == ea2 && jj < ei2);
        ei2 = lt1 ? ei1 : (lt2 ? jj : ei2);
        ea2 = lt1 ? ea1 : (lt2 ? d  : ea2);
        ei1 = lt0 ? ei0 : (lt1 ? jj : ei1);
        ea1 = lt0 ? ea0 : (lt1 ? d  : ea1);
        ei0 = lt0 ? jj : ei0;
        ea0 = lt0 ? d  : ea0;
    }

    {
        float w0 = __fdiv_rn(1.0f, fmaxf(ea0, 1e-16f));
        float w1 = __fdiv_rn(1.0f, fmaxf(ea1, 1e-16f));
        float w2 = __fdiv_rn(1.0f, fmaxf(ea2, 1e-16f));
        float den = __fadd_rn(__fadd_rn(w0, w1), w2);
        sI[0][tid] = ei0; sI[1][tid] = ei1; sI[2][tid] = ei2;
        sW[0][tid] = w0;  sW[1][tid] = w1;  sW[2][tid] = w2;
        sW[3][tid] = __fdiv_rn(1.0f, den);   // hoisted inverse
    }
    __syncthreads();

    // ---- warp-cooperative float4 interpolation + split-bf16 write ----
    const int w    = tid >> 5;
    const int lane = tid & 31;
    for (int p = 0; p < 32; ++p) {
        const int slot = w * 32 + p;
        const int mm   = b * NDST + blockIdx.x * PTS_PER_BLK + slot;
        const int j0 = sI[0][slot], j1 = sI[1][slot], j2 = sI[2][slot];
        const float w0 = sW[0][slot], w1 = sW[1][slot], w2 = sW[2][slot];
        const float inv = sW[3][slot];

        const float4* x0 = (const float4*)(x + ((size_t)b * NSRC + j0) * CIN);
        const float4* x1 = (const float4*)(x + ((size_t)b * NSRC + j1) * CIN);
        const float4* x2 = (const float4*)(x + ((size_t)b * NSRC + j2) * CIN);
        uint2* xh = (uint2*)(g_xin_hi + (size_t)mm * CCAT);
        uint2* xl = (uint2*)(g_xin_lo + (size_t)mm * CCAT);

#pragma unroll
        for (int i = 0; i < CIN / 128; ++i) {      // 2 iterations
            const int c4 = i * 32 + lane;          // float4 index
            float4 a0 = x0[c4], a1 = x1[c4], a2 = x2[c4];
            float v[4];
            v[0] = __fmul_rn(__fadd_rn(__fadd_rn(__fmul_rn(w0, a0.x), __fmul_rn(w1, a1.x)), __fmul_rn(w2, a2.x)), inv);
            v[1] = __fmul_rn(__fadd_rn(__fadd_rn(__fmul_rn(w0, a0.y), __fmul_rn(w1, a1.y)), __fmul_rn(w2, a2.y)), inv);
            v[2] = __fmul_rn(__fadd_rn(__fadd_rn(__fmul_rn(w0, a0.z), __fmul_rn(w1, a1.z)), __fmul_rn(w2, a2.z)), inv);
            v[3] = __fmul_rn(__fadd_rn(__fadd_rn(__fmul_rn(w0, a0.w), __fmul_rn(w1, a1.w)), __fmul_rn(w2, a2.w)), inv);
            uint16_t h[4], l[4];
#pragma unroll
            for (int q = 0; q < 4; ++q) split_bf16(v[q], h[q], l[q]);
            xh[c4] = make_uint2((uint32_t)h[0] | ((uint32_t)h[1] << 16),
                                (uint32_t)h[2] | ((uint32_t)h[3] << 16));
            xl[c4] = make_uint2((uint32_t)l[0] | ((uint32_t)l[1] << 16),
                                (uint32_t)l[2] | ((uint32_t)l[3] << 16));
        }
        {   // x_skip: 128 channels, 1 float4 iteration
            const float4* xs = (const float4*)(x_skip + (size_t)mm * CSKIP);
            float4 s = xs[lane];
            uint16_t h[4], l[4];
            split_bf16(s.x, h[0], l[0]);
            split_bf16(s.y, h[1], l[1]);
            split_bf16(s.z, h[2], l[2]);
            split_bf16(s.w, h[3], l[3]);
            uint2* xh2 = (uint2*)(g_xin_hi + (size_t)mm * CCAT + CIN);
            uint2* xl2 = (uint2*)(g_xin_lo + (size_t)mm * CCAT + CIN);
            xh2[lane] = make_uint2((uint32_t)h[0] | ((uint32_t)h[1] << 16),
                                   (uint32_t)h[2] | ((uint32_t)h[3] << 16));
            xl2[lane] = make_uint2((uint32_t)l[0] | ((uint32_t)l[1] << 16),
                                   (uint32_t)l[2] | ((uint32_t)l[3] << 16));
        }
    }
}

// ---------------------------------------------------------------------------
// WMMA split-bf16 GEMM:  C[M,N] = epi(A @ B^T + bias)
//   cp.async double-buffered staging, conflict-free 80B smem stride.
//   Block tile 128x128, 8 warps, warp tile 32x64.
//   3-term split: AhBh + AhBl + AlBh, fp32 accumulate.
// ---------------------------------------------------------------------------
#define BK_G   32
#define STRD   40                          // 80B row stride: conflict-free LDSM
#define PL_B   (128 * STRD * 2)            // plane bytes = 10240
#define BUF_B  (4 * PL_B)                  // 4 planes per buffer = 40960
#define CSTR   68                          // epilogue C buffer stride (floats)

template<int N, int KTOT, int EPI>
__global__ __launch_bounds__(256, 2)
void wmma_gemm_kernel(const __nv_bfloat16* __restrict__ Ah,
                      const __nv_bfloat16* __restrict__ Al,
                      const __nv_bfloat16* __restrict__ Bh,
                      const __nv_bfloat16* __restrict__ Bl,
                      const float* __restrict__ bias,
                      float* __restrict__ outp) {
    constexpr int NC = KTOT / BK_G;
    extern __shared__ char smem[];
    const uint32_t sbase = (uint32_t)__cvta_generic_to_shared(smem);

    const int tid  = threadIdx.x;
    const int w    = tid >> 5;
    const int lane = tid & 31;
    const int bm   = blockIdx.y * 128;
    const int bn   = blockIdx.x * 128;
    const int wm   = (w & 3) * 32;
    const int wn   = (w >> 2) * 64;

    auto stage = [&](int kc, int buf) {
#pragma unroll
        for (int u = tid; u < 2048; u += 256) {
            const int plane = u >> 9;
            const int idx   = u & 511;
            const int row   = idx >> 2;
            const int c     = idx & 3;
            const __nv_bfloat16* P =
                (plane == 0) ? Ah : (plane == 1) ? Al : (plane == 2) ? Bh : Bl;
            const int grow = (plane < 2) ? (bm + row) : (bn + row);
            const __nv_bfloat16* gsrc =
                P + (size_t)grow * KTOT + kc * BK_G + c * 8;
            uint32_t sdst = sbase + buf * BUF_B + plane * PL_B +
                            row * (STRD * 2) + c * 16;
            cp_async16(sdst, gsrc);
        }
    };

    wmma::fragment<wmma::accumulator, 16, 16, 16, float> acc[2][4];
#pragma unroll
    for (int i = 0; i < 2; ++i)
#pragma unroll
        for (int j = 0; j < 4; ++j)
            wmma::fill_fragment(acc[i][j], 0.0f);

    stage(0, 0);
    CP_COMMIT();

    for (int kc = 0; kc < NC; ++kc) {
        if (kc + 1 < NC) {
            stage(kc + 1, (kc + 1) & 1);
            CP_COMMIT();
            CP_WAIT(1);
        } else {
            CP_WAIT(0);
        }
        __syncthreads();

        const __nv_bfloat16* sb =
            (const __nv_bfloat16*)(smem + (kc & 1) * BUF_B);
        const __nv_bfloat16* sAh = sb;
        const __nv_bfloat16* sAl = sb + 128 * STRD;
        const __nv_bfloat16* sBh = sb + 2 * 128 * STRD;
        const __nv_bfloat16* sBl = sb + 3 * 128 * STRD;

#pragma unroll
        for (int kk = 0; kk < BK_G; kk += 16) {
            wmma::fragment<wmma::matrix_a, 16, 16, 16, __nv_bfloat16,
                           wmma::row_major> a_h[2], a_l[2];
#pragma unroll
            for (int i = 0; i < 2; ++i) {
                wmma::load_matrix_sync(a_h[i], sAh + (wm + i * 16) * STRD + kk, STRD);
                wmma::load_matrix_sync(a_l[i], sAl + (wm + i * 16) * STRD + kk, STRD);
            }
#pragma unroll
            for (int j = 0; j < 4; ++j) {
                wmma::fragment<wmma::matrix_b, 16, 16, 16, __nv_bfloat16,
                               wmma::col_major> b_h, b_l;
                wmma::load_matrix_sync(b_h, sBh + (wn + j * 16) * STRD + kk, STRD);
                wmma::load_matrix_sync(b_l, sBl + (wn + j * 16) * STRD + kk, STRD);
#pragma unroll
                for (int i = 0; i < 2; ++i) {
                    wmma::mma_sync(acc[i][j], a_h[i], b_h, acc[i][j]);
                    wmma::mma_sync(acc[i][j], a_h[i], b_l, acc[i][j]);
                    wmma::mma_sync(acc[i][j], a_l[i], b_h, acc[i][j]);
                }
            }
        }
        __syncthreads();
    }

    // epilogue: dump accumulators through per-warp shared slice
    float* cw = (float*)smem + w * (32 * CSTR);
#pragma unroll
    for (int i = 0; i < 2; ++i)
#pragma unroll
        for (int j = 0; j < 4; ++j)
            wmma::store_matrix_sync(cw + i * 16 * CSTR + j * 16, acc[i][j],
                                    CSTR, wmma::mem_row_major);
    __syncwarp();

    const int m = bm + wm + lane;
    const int ncol0 = bn + wn;
    if (EPI == 0) {
        uint32_t* dh = (uint32_t*)(g_h1_hi + (size_t)m * N + ncol0);
        uint32_t* dl = (uint32_t*)(g_h1_lo + (size_t)m * N + ncol0);
#pragma unroll
        for (int c = 0; c < 64; c += 2) {
            float v0 = fmaxf(cw[lane * CSTR + c]     + bias[ncol0 + c],     0.0f);
            float v1 = fmaxf(cw[lane * CSTR + c + 1] + bias[ncol0 + c + 1], 0.0f);
            uint16_t h0, l0, h1, l1;
            split_bf16(v0, h0, l0);
            split_bf16(v1, h1, l1);
            dh[c >> 1] = (uint32_t)h0 | ((uint32_t)h1 << 16);
            dl[c >> 1] = (uint32_t)l0 | ((uint32_t)l1 << 16);
        }
    } else {
        const int batch = m >> 13;
        const float* gt = g_gate + batch * COUT;
        float4* dst = (float4*)(outp + (size_t)m * N + ncol0);
#pragma unroll
        for (int c = 0; c < 64; c += 4) {
            float4 o;
            o.x = (cw[lane * CSTR + c]     + bias[ncol0 + c])     * gt[ncol0 + c];
            o.y = (cw[lane * CSTR + c + 1] + bias[ncol0 + c + 1]) * gt[ncol0 + c + 1];
            o.z = (cw[lane * CSTR + c + 2] + bias[ncol0 + c + 2]) * gt[ncol0 + c + 2];
            o.w = (cw[lane * CSTR + c + 3] + bias[ncol0 + c + 3]) * gt[ncol0 + c + 3];
            dst[c >> 2] = o;
        }
    }
}

// ---------------------------------------------------------------------------
// Tail: pos_skip and batch_skip into concatenated output
// ---------------------------------------------------------------------------
__global__ void tail_kernel(const float* __restrict__ pos_skip,
                            float* __restrict__ out, int mode, int out_size) {
    int i = blockIdx.x * 256 + threadIdx.x;
    if (i < POS_ELEMS && OUT_ELEMS + i < out_size)
        out[OUT_ELEMS + i] = pos_skip[i];
    if (i < MTOT) {
        if (mode == 1) {
            int o = OUT_ELEMS + POS_ELEMS + i;
            if (o < out_size) out[o] = (float)(i >> 13);
        } else if (mode == 2) {
            int o = OUT_ELEMS + POS_ELEMS + 2 * i;
            if (o + 1 < out_size)
                ((long long*)(out + OUT_ELEMS + POS_ELEMS))[i] = (long long)(i >> 13);
        }
    }
}

// ---------------------------------------------------------------------------
extern "C" void kernel_launch(void* const* d_in, const int* in_sizes, int n_in,
                              void* d_out, int out_size) {
    const float* par      = (const float*)d_in[0];
    const float* x        = (const float*)d_in[1];
    const float* pos      = (const float*)d_in[2];
    const float* x_skip   = (const float*)d_in[3];
    const float* pos_skip = (const float*)d_in[4];
    const float* W1       = (const float*)d_in[5];
    const float* b1       = (const float*)d_in[6];
    const float* W2       = (const float*)d_in[7];
    const float* b2       = (const float*)d_in[8];
    const float* Wp       = (const float*)d_in[9];
    const float* bp       = (const float*)d_in[10];
    float* out = (float*)d_out;

    __nv_bfloat16 *p_xh, *p_xl, *p_hh, *p_hl, *p_w1h, *p_w1l, *p_w2h, *p_w2l;
    cudaGetSymbolAddress((void**)&p_xh,  g_xin_hi);
    cudaGetSymbolAddress((void**)&p_xl,  g_xin_lo);
    cudaGetSymbolAddress((void**)&p_hh,  g_h1_hi);
    cudaGetSymbolAddress((void**)&p_hl,  g_h1_lo);
    cudaGetSymbolAddress((void**)&p_w1h, g_w1t_hi);
    cudaGetSymbolAddress((void**)&p_w1l, g_w1t_lo);
    cudaGetSymbolAddress((void**)&p_w2h, g_w2t_hi);
    cudaGetSymbolAddress((void**)&p_w2l, g_w2t_lo);

    constexpr int SMEM_G = 2 * BUF_B;   // 81920
    cudaFuncSetAttribute(wmma_gemm_kernel<HDIM, CCAT, 0>,
                         cudaFuncAttributeMaxDynamicSharedMemorySize, SMEM_G);
    cudaFuncSetAttribute(wmma_gemm_kernel<COUT, HDIM, 1>,
                         cudaFuncAttributeMaxDynamicSharedMemorySize, SMEM_G);

    prep_kernel<<<(CCAT * HDIM + 255) / 256, 256>>>(par, Wp, bp, W1, W2);

    dim3 kg(NDST / PTS_PER_BLK, NB);       // (32, 4)
    knn_interp_kernel<<<kg, 256>>>(x, pos, x_skip, pos_skip);

    dim3 g1(HDIM / 128, MTOT / 128);       // (2, 256)
    wmma_gemm_kernel<HDIM, CCAT, 0><<<g1, 256, SMEM_G>>>(
        p_xh, p_xl, p_w1h, p_w1l, b1, nullptr);

    dim3 g2(COUT / 128, MTOT / 128);       // (1, 256)
    wmma_gemm_kernel<COUT, HDIM, 1><<<g2, 256, SMEM_G>>>(
        p_hh, p_hl, p_w2h, p_w2l, b2, out);

    const int tail = out_size - OUT_ELEMS;
    if (tail > 0) {
        int mode = 0;
        if (tail >= POS_ELEMS + 2 * MTOT)      mode = 2;
        else if (tail >= POS_ELEMS + MTOT)     mode = 1;
        tail_kernel<<<(POS_ELEMS + 255) / 256, 256>>>(pos_skip, out, mode, out_size);
    }
}

// round 11
// speedup vs baseline: 1.9203x; 1.0484x over previous
#include <cuda_runtime.h>
#include <cuda_bf16.h>
#include <math_constants.h>
#include <cstdint>
#include <mma.h>

using namespace nvcuda;

#define NB     4
#define NSRC   2048
#define NDST   8192
#define CIN    256
#define CSKIP  128
#define CCAT   384
#define HDIM   256
#define COUT   128
#define PDIM   64
#define MTOT   (NB * NDST)          // 32768

#define OUT_ELEMS   (MTOT * COUT)   // 4194304
#define POS_ELEMS   (MTOT * 3)      // 98304

// ---------------------------------------------------------------------------
// Scratch (__device__ globals; no allocations allowed)
// ---------------------------------------------------------------------------
__device__ __nv_bfloat16 g_xin_hi[MTOT * CCAT];   // A1 hi plane, [M,K] K-major
__device__ __nv_bfloat16 g_xin_lo[MTOT * CCAT];
__device__ __nv_bfloat16 g_h1_hi[MTOT * HDIM];    // A2 hi plane
__device__ __nv_bfloat16 g_h1_lo[MTOT * HDIM];
__device__ __nv_bfloat16 g_w1t_hi[HDIM * CCAT];   // B1 [N=256, K=384]
__device__ __nv_bfloat16 g_w1t_lo[HDIM * CCAT];
__device__ __nv_bfloat16 g_w2t_hi[COUT * HDIM];   // B2 [N=128, K=256]
__device__ __nv_bfloat16 g_w2t_lo[COUT * HDIM];
__device__ float g_gate[NB * COUT];

// fp32 -> bf16 hi/lo split
__device__ __forceinline__ void split_bf16(float v, uint16_t& h, uint16_t& l) {
    __nv_bfloat16 hb = __float2bfloat16_rn(v);
    float r = v - __bfloat162float(hb);
    __nv_bfloat16 lb = __float2bfloat16_rn(r);
    h = __bfloat16_as_ushort(hb);
    l = __bfloat16_as_ushort(lb);
}

// cp.async helpers (sm_80 baseline — legal on sm_103 target)
__device__ __forceinline__ void cp_async16(uint32_t dst, const void* src) {
    asm volatile("cp.async.ca.shared.global [%0], [%1], 16;"
                 :: "r"(dst), "l"(src) : "memory");
}
#define CP_COMMIT() asm volatile("cp.async.commit_group;" ::: "memory")
#define CP_WAIT(n)  asm volatile("cp.async.wait_group %0;" :: "n"(n) : "memory")

// ---------------------------------------------------------------------------
// gate + weight prep fused
// ---------------------------------------------------------------------------
__global__ void prep_kernel(const float* __restrict__ par,
                            const float* __restrict__ Wp,
                            const float* __restrict__ bp,
                            const float* __restrict__ W1,
                            const float* __restrict__ W2) {
    int i = blockIdx.x * 256 + threadIdx.x;
    if (i < NB * COUT) {
        int b = i >> 7, n = i & 127;
        float acc = bp[n];
        const float* pe = par + b * PDIM;
#pragma unroll
        for (int p = 0; p < PDIM; ++p)
            acc = fmaf(pe[p], Wp[p * COUT + n], acc);
        g_gate[i] = fmaxf(acc, 0.0f);
    }
    if (i < CCAT * HDIM) {
        int k = i / HDIM, n = i % HDIM;
        uint16_t h, l;
        split_bf16(W1[i], h, l);
        g_w1t_hi[n * CCAT + k] = __ushort_as_bfloat16(h);
        g_w1t_lo[n * CCAT + k] = __ushort_as_bfloat16(l);
    }
    if (i < HDIM * COUT) {
        int k = i / COUT, n = i % COUT;
        uint16_t h, l;
        split_bf16(W2[i], h, l);
        g_w2t_hi[n * HDIM + k] = __ushort_as_bfloat16(h);
        g_w2t_lo[n * HDIM + k] = __ushort_as_bfloat16(l);
    }
}

// ---------------------------------------------------------------------------
// KNN (k=3) + inverse-squared-distance interpolate + concat x_skip.
//
// THREAD-PAIR per point: even thread scans even candidates, odd thread
// scans odd candidates (halved per-thread instruction count); merged via
// shfl with lowest-index tie-break == sequential-stable top_k semantics.
// d2 rounding matches the reference bit-exactly (R5-validated):
//   s2  = fma(z,z, fma(y,y, rn(x*x)))
//   dot = fma(dz,sz, fma(dy,sy, rn(dx*sx)))
//   d2  = rn( rn(dd + s2) - rn(2*dot) )
// Interpolation: float4 gathers, division hoisted to 1/den per point.
// ---------------------------------------------------------------------------
#define PTS_PER_BLK 128

__global__ __launch_bounds__(256)
void knn_interp_kernel(const float* __restrict__ x,
                       const float* __restrict__ pos,
                       const float* __restrict__ x_skip,
                       const float* __restrict__ pos_skip) {
    __shared__ float4 spos[NSRC];                 // (x, y, z, s2)  32 KB
    __shared__ int   sI[3][PTS_PER_BLK];
    __shared__ float sW[4][PTS_PER_BLK];          // w0, w1, w2, inv_den

    const int b   = blockIdx.y;
    const int tid = threadIdx.x;

    const float* sp = pos + (size_t)b * NSRC * 3;
    for (int i = tid; i < NSRC; i += 256) {
        float px = sp[i * 3 + 0];
        float py = sp[i * 3 + 1];
        float pz = sp[i * 3 + 2];
        float s2 = __fmaf_rn(pz, pz, __fmaf_rn(py, py, __fmul_rn(px, px)));
        spos[i] = make_float4(px, py, pz, s2);
    }
    __syncthreads();

    const int slot   = tid >> 1;                  // point slot 0..127
    const int parity = tid & 1;                   // candidate parity class
    const int pt = blockIdx.x * PTS_PER_BLK + slot;
    const int m  = b * NDST + pt;
    const float dx = pos_skip[m * 3 + 0];
    const float dy = pos_skip[m * 3 + 1];
    const float dz = pos_skip[m * 3 + 2];
    const float dd = __fmaf_rn(dz, dz, __fmaf_rn(dy, dy, __fmul_rn(dx, dx)));

    float a0 = CUDART_INF_F, a1 = CUDART_INF_F, a2 = CUDART_INF_F;
    int   q0 = 0, q1 = 0, q2 = 0;

#pragma unroll 4
    for (int j = parity; j < NSRC; j += 2) {
        float4 c = spos[j];
        float d2 = __fadd_rn(__fadd_rn(dd, c.w),
                   -__fmul_rn(2.0f,
                    __fmaf_rn(dz, c.z, __fmaf_rn(dy, c.y, __fmul_rn(dx, c.x)))));
        bool p0 = d2 < a0, p1 = d2 < a1, p2 = d2 < a2;
        q2 = p1 ? q1 : (p2 ? j  : q2);
        a2 = p1 ? a1 : (p2 ? d2 : a2);
        q1 = p0 ? q0 : (p1 ? j  : q1);
        a1 = p0 ? a0 : (p1 ? d2 : a1);
        q0 = p0 ? j  : q0;
        a0 = p0 ? d2 : a0;
    }

    // pair merge: even lane receives odd lane's top-3, merges with index
    // tie-break (exact sequential-stable semantics)
    const unsigned FULL = 0xffffffffu;
    float oa0 = __shfl_down_sync(FULL, a0, 1);
    float oa1 = __shfl_down_sync(FULL, a1, 1);
    float oa2 = __shfl_down_sync(FULL, a2, 1);
    int   oq0 = __shfl_down_sync(FULL, q0, 1);
    int   oq1 = __shfl_down_sync(FULL, q1, 1);
    int   oq2 = __shfl_down_sync(FULL, q2, 1);

    if (parity == 0) {
#pragma unroll
        for (int t = 0; t < 3; ++t) {
            float d  = (t == 0) ? oa0 : (t == 1) ? oa1 : oa2;
            int   jj = (t == 0) ? oq0 : (t == 1) ? oq1 : oq2;
            bool lt0 = (d < a0) || (d == a0 && jj < q0);
            bool lt1 = (d < a1) || (d == a1 && jj < q1);
            bool lt2 = (d < a2) || (d == a2 && jj < q2);
            q2 = lt1 ? q1 : (lt2 ? jj : q2);
            a2 = lt1 ? a1 : (lt2 ? d  : a2);
            q1 = lt0 ? q0 : (lt1 ? jj : q1);
            a1 = lt0 ? a0 : (lt1 ? d  : a1);
            q0 = lt0 ? jj : q0;
            a0 = lt0 ? d  : a0;
        }
        float w0 = __fdiv_rn(1.0f, fmaxf(a0, 1e-16f));
        float w1 = __fdiv_rn(1.0f, fmaxf(a1, 1e-16f));
        float w2 = __fdiv_rn(1.0f, fmaxf(a2, 1e-16f));
        float den = __fadd_rn(__fadd_rn(w0, w1), w2);
        sI[0][slot] = q0; sI[1][slot] = q1; sI[2][slot] = q2;
        sW[0][slot] = w0; sW[1][slot] = w1; sW[2][slot] = w2;
        sW[3][slot] = __fdiv_rn(1.0f, den);
    }
    __syncthreads();

    // ---- warp-cooperative float4 interpolation + split-bf16 write ----
    const int w    = tid >> 5;
    const int lane = tid & 31;
    for (int p = 0; p < PTS_PER_BLK / 8; ++p) {    // 16 points per warp
        const int sl = w * (PTS_PER_BLK / 8) + p;
        const int mm = b * NDST + blockIdx.x * PTS_PER_BLK + sl;
        const int j0 = sI[0][sl], j1 = sI[1][sl], j2 = sI[2][sl];
        const float w0 = sW[0][sl], w1 = sW[1][sl], w2 = sW[2][sl];
        const float inv = sW[3][sl];

        const float4* x0 = (const float4*)(x + ((size_t)b * NSRC + j0) * CIN);
        const float4* x1 = (const float4*)(x + ((size_t)b * NSRC + j1) * CIN);
        const float4* x2 = (const float4*)(x + ((size_t)b * NSRC + j2) * CIN);
        uint2* xh = (uint2*)(g_xin_hi + (size_t)mm * CCAT);
        uint2* xl = (uint2*)(g_xin_lo + (size_t)mm * CCAT);

#pragma unroll
        for (int i = 0; i < CIN / 128; ++i) {      // 2 iterations
            const int c4 = i * 32 + lane;
            float4 v0 = x0[c4], v1 = x1[c4], v2 = x2[c4];
            float v[4];
            v[0] = __fmul_rn(__fadd_rn(__fadd_rn(__fmul_rn(w0, v0.x), __fmul_rn(w1, v1.x)), __fmul_rn(w2, v2.x)), inv);
            v[1] = __fmul_rn(__fadd_rn(__fadd_rn(__fmul_rn(w0, v0.y), __fmul_rn(w1, v1.y)), __fmul_rn(w2, v2.y)), inv);
            v[2] = __fmul_rn(__fadd_rn(__fadd_rn(__fmul_rn(w0, v0.z), __fmul_rn(w1, v1.z)), __fmul_rn(w2, v2.z)), inv);
            v[3] = __fmul_rn(__fadd_rn(__fadd_rn(__fmul_rn(w0, v0.w), __fmul_rn(w1, v1.w)), __fmul_rn(w2, v2.w)), inv);
            uint16_t h[4], l[4];
#pragma unroll
            for (int q = 0; q < 4; ++q) split_bf16(v[q], h[q], l[q]);
            xh[c4] = make_uint2((uint32_t)h[0] | ((uint32_t)h[1] << 16),
                                (uint32_t)h[2] | ((uint32_t)h[3] << 16));
            xl[c4] = make_uint2((uint32_t)l[0] | ((uint32_t)l[1] << 16),
                                (uint32_t)l[2] | ((uint32_t)l[3] << 16));
        }
        {   // x_skip: 128 channels, 1 float4 iteration
            const float4* xs = (const float4*)(x_skip + (size_t)mm * CSKIP);
            float4 s = xs[lane];
            uint16_t h[4], l[4];
            split_bf16(s.x, h[0], l[0]);
            split_bf16(s.y, h[1], l[1]);
            split_bf16(s.z, h[2], l[2]);
            split_bf16(s.w, h[3], l[3]);
            uint2* xh2 = (uint2*)(g_xin_hi + (size_t)mm * CCAT + CIN);
            uint2* xl2 = (uint2*)(g_xin_lo + (size_t)mm * CCAT + CIN);
            xh2[lane] = make_uint2((uint32_t)h[0] | ((uint32_t)h[1] << 16),
                                   (uint32_t)h[2] | ((uint32_t)h[3] << 16));
            xl2[lane] = make_uint2((uint32_t)l[0] | ((uint32_t)l[1] << 16),
                                   (uint32_t)l[2] | ((uint32_t)l[3] << 16));
        }
    }
}

// ---------------------------------------------------------------------------
// WMMA split-bf16 GEMM:  C[M,N] = epi(A @ B^T + bias)
//   cp.async double-buffered staging, conflict-free 80B smem stride.
//   Block tile 128x128, 8 warps, warp tile 32x64.
//   3-term split, term-major issue order (RAW dep distance >= 2).
// ---------------------------------------------------------------------------
#define BK_G   32
#define STRD   40                          // 80B row stride: conflict-free LDSM
#define PL_B   (128 * STRD * 2)            // plane bytes = 10240
#define BUF_B  (4 * PL_B)                  // 4 planes per buffer = 40960
#define CSTR   68                          // epilogue C buffer stride (floats)

template<int N, int KTOT, int EPI>
__global__ __launch_bounds__(256, 2)
void wmma_gemm_kernel(const __nv_bfloat16* __restrict__ Ah,
                      const __nv_bfloat16* __restrict__ Al,
                      const __nv_bfloat16* __restrict__ Bh,
                      const __nv_bfloat16* __restrict__ Bl,
                      const float* __restrict__ bias,
                      float* __restrict__ outp) {
    constexpr int NC = KTOT / BK_G;
    extern __shared__ char smem[];
    const uint32_t sbase = (uint32_t)__cvta_generic_to_shared(smem);

    const int tid  = threadIdx.x;
    const int w    = tid >> 5;
    const int lane = tid & 31;
    const int bm   = blockIdx.y * 128;
    const int bn   = blockIdx.x * 128;
    const int wm   = (w & 3) * 32;
    const int wn   = (w >> 2) * 64;

    auto stage = [&](int kc, int buf) {
#pragma unroll
        for (int u = tid; u < 2048; u += 256) {
            const int plane = u >> 9;
            const int idx   = u & 511;
            const int row   = idx >> 2;
            const int c     = idx & 3;
            const __nv_bfloat16* P =
                (plane == 0) ? Ah : (plane == 1) ? Al : (plane == 2) ? Bh : Bl;
            const int grow = (plane < 2) ? (bm + row) : (bn + row);
            const __nv_bfloat16* gsrc =
                P + (size_t)grow * KTOT + kc * BK_G + c * 8;
            uint32_t sdst = sbase + buf * BUF_B + plane * PL_B +
                            row * (STRD * 2) + c * 16;
            cp_async16(sdst, gsrc);
        }
    };

    wmma::fragment<wmma::accumulator, 16, 16, 16, float> acc[2][4];
#pragma unroll
    for (int i = 0; i < 2; ++i)
#pragma unroll
        for (int j = 0; j < 4; ++j)
            wmma::fill_fragment(acc[i][j], 0.0f);

    stage(0, 0);
    CP_COMMIT();

    for (int kc = 0; kc < NC; ++kc) {
        if (kc + 1 < NC) {
            stage(kc + 1, (kc + 1) & 1);
            CP_COMMIT();
            CP_WAIT(1);
        } else {
            CP_WAIT(0);
        }
        __syncthreads();

        const __nv_bfloat16* sb =
            (const __nv_bfloat16*)(smem + (kc & 1) * BUF_B);
        const __nv_bfloat16* sAh = sb;
        const __nv_bfloat16* sAl = sb + 128 * STRD;
        const __nv_bfloat16* sBh = sb + 2 * 128 * STRD;
        const __nv_bfloat16* sBl = sb + 3 * 128 * STRD;

#pragma unroll
        for (int kk = 0; kk < BK_G; kk += 16) {
            wmma::fragment<wmma::matrix_a, 16, 16, 16, __nv_bfloat16,
                           wmma::row_major> a_h[2], a_l[2];
#pragma unroll
            for (int i = 0; i < 2; ++i) {
                wmma::load_matrix_sync(a_h[i], sAh + (wm + i * 16) * STRD + kk, STRD);
                wmma::load_matrix_sync(a_l[i], sAl + (wm + i * 16) * STRD + kk, STRD);
            }
#pragma unroll
            for (int j = 0; j < 4; ++j) {
                wmma::fragment<wmma::matrix_b, 16, 16, 16, __nv_bfloat16,
                               wmma::col_major> b_h, b_l;
                wmma::load_matrix_sync(b_h, sBh + (wn + j * 16) * STRD + kk, STRD);
                wmma::load_matrix_sync(b_l, sBl + (wn + j * 16) * STRD + kk, STRD);
                // term-major: RAW distance on each acc >= 2
                wmma::mma_sync(acc[0][j], a_h[0], b_h, acc[0][j]);
                wmma::mma_sync(acc[1][j], a_h[1], b_h, acc[1][j]);
                wmma::mma_sync(acc[0][j], a_h[0], b_l, acc[0][j]);
                wmma::mma_sync(acc[1][j], a_h[1], b_l, acc[1][j]);
                wmma::mma_sync(acc[0][j], a_l[0], b_h, acc[0][j]);
                wmma::mma_sync(acc[1][j], a_l[1], b_h, acc[1][j]);
            }
        }
        __syncthreads();
    }

    // epilogue: dump accumulators through per-warp shared slice
    float* cw = (float*)smem + w * (32 * CSTR);
#pragma unroll
    for (int i = 0; i < 2; ++i)
#pragma unroll
        for (int j = 0; j < 4; ++j)
            wmma::store_matrix_sync(cw + i * 16 * CSTR + j * 16, acc[i][j],
                                    CSTR, wmma::mem_row_major);
    __syncwarp();

    const int m = bm + wm + lane;
    const int ncol0 = bn + wn;
    if (EPI == 0) {
        uint32_t* dh = (uint32_t*)(g_h1_hi + (size_t)m * N + ncol0);
        uint32_t* dl = (uint32_t*)(g_h1_lo + (size_t)m * N + ncol0);
#pragma unroll
        for (int c = 0; c < 64; c += 2) {
            float v0 = fmaxf(cw[lane * CSTR + c]     + bias[ncol0 + c],     0.0f);
            float v1 = fmaxf(cw[lane * CSTR + c + 1] + bias[ncol0 + c + 1], 0.0f);
            uint16_t h0, l0, h1, l1;
            split_bf16(v0, h0, l0);
            split_bf16(v1, h1, l1);
            dh[c >> 1] = (uint32_t)h0 | ((uint32_t)h1 << 16);
            dl[c >> 1] = (uint32_t)l0 | ((uint32_t)l1 << 16);
        }
    } else {
        const int batch = m >> 13;
        const float* gt = g_gate + batch * COUT;
        float4* dst = (float4*)(outp + (size_t)m * N + ncol0);
#pragma unroll
        for (int c = 0; c < 64; c += 4) {
            float4 o;
            o.x = (cw[lane * CSTR + c]     + bias[ncol0 + c])     * gt[ncol0 + c];
            o.y = (cw[lane * CSTR + c + 1] + bias[ncol0 + c + 1]) * gt[ncol0 + c + 1];
            o.z = (cw[lane * CSTR + c + 2] + bias[ncol0 + c + 2]) * gt[ncol0 + c + 2];
            o.w = (cw[lane * CSTR + c + 3] + bias[ncol0 + c + 3]) * gt[ncol0 + c + 3];
            dst[c >> 2] = o;
        }
    }
}

// ---------------------------------------------------------------------------
// Tail: pos_skip and batch_skip into concatenated output
// ---------------------------------------------------------------------------
__global__ void tail_kernel(const float* __restrict__ pos_skip,
                            float* __restrict__ out, int mode, int out_size) {
    int i = blockIdx.x * 256 + threadIdx.x;
    if (i < POS_ELEMS && OUT_ELEMS + i < out_size)
        out[OUT_ELEMS + i] = pos_skip[i];
    if (i < MTOT) {
        if (mode == 1) {
            int o = OUT_ELEMS + POS_ELEMS + i;
            if (o < out_size) out[o] = (float)(i >> 13);
        } else if (mode == 2) {
            int o = OUT_ELEMS + POS_ELEMS + 2 * i;
            if (o + 1 < out_size)
                ((long long*)(out + OUT_ELEMS + POS_ELEMS))[i] = (long long)(i >> 13);
        }
    }
}

// ---------------------------------------------------------------------------
extern "C" void kernel_launch(void* const* d_in, const int* in_sizes, int n_in,
                              void* d_out, int out_size) {
    const float* par      = (const float*)d_in[0];
    const float* x        = (const float*)d_in[1];
    const float* pos      = (const float*)d_in[2];
    const float* x_skip   = (const float*)d_in[3];
    const float* pos_skip = (const float*)d_in[4];
    const float* W1       = (const float*)d_in[5];
    const float* b1       = (const float*)d_in[6];
    const float* W2       = (const float*)d_in[7];
    const float* b2       = (const float*)d_in[8];
    const float* Wp       = (const float*)d_in[9];
    const float* bp       = (const float*)d_in[10];
    float* out = (float*)d_out;

    __nv_bfloat16 *p_xh, *p_xl, *p_hh, *p_hl, *p_w1h, *p_w1l, *p_w2h, *p_w2l;
    cudaGetSymbolAddress((void**)&p_xh,  g_xin_hi);
    cudaGetSymbolAddress((void**)&p_xl,  g_xin_lo);
    cudaGetSymbolAddress((void**)&p_hh,  g_h1_hi);
    cudaGetSymbolAddress((void**)&p_hl,  g_h1_lo);
    cudaGetSymbolAddress((void**)&p_w1h, g_w1t_hi);
    cudaGetSymbolAddress((void**)&p_w1l, g_w1t_lo);
    cudaGetSymbolAddress((void**)&p_w2h, g_w2t_hi);
    cudaGetSymbolAddress((void**)&p_w2l, g_w2t_lo);

    constexpr int SMEM_G = 2 * BUF_B;   // 81920
    cudaFuncSetAttribute(wmma_gemm_kernel<HDIM, CCAT, 0>,
                         cudaFuncAttributeMaxDynamicSharedMemorySize, SMEM_G);
    cudaFuncSetAttribute(wmma_gemm_kernel<COUT, HDIM, 1>,
                         cudaFuncAttributeMaxDynamicSharedMemorySize, SMEM_G);

    prep_kernel<<<(CCAT * HDIM + 255) / 256, 256>>>(par, Wp, bp, W1, W2);

    dim3 kg(NDST / PTS_PER_BLK, NB);       // (64, 4) = 256 CTAs
    knn_interp_kernel<<<kg, 256>>>(x, pos, x_skip, pos_skip);

    dim3 g1(HDIM / 128, MTOT / 128);       // (2, 256)
    wmma_gemm_kernel<HDIM, CCAT, 0><<<g1, 256, SMEM_G>>>(
        p_xh, p_xl, p_w1h, p_w1l, b1, nullptr);

    dim3 g2(COUT / 128, MTOT / 128);       // (1, 256)
    wmma_gemm_kernel<COUT, HDIM, 1><<<g2, 256, SMEM_G>>>(
        p_hh, p_hl, p_w2h, p_w2l, b2, out);

    const int tail = out_size - OUT_ELEMS;
    if (tail > 0) {
        int mode = 0;
        if (tail >= POS_ELEMS + 2 * MTOT)      mode = 2;
        else if (tail >= POS_ELEMS + MTOT)     mode = 1;
        tail_kernel<<<(POS_ELEMS + 255) / 256, 256>>>(pos_skip, out, mode, out_size);
    }
}

// round 12
// speedup vs baseline: 1.9745x; 1.0282x over previous
#include <cuda_runtime.h>
#include <cuda_bf16.h>
#include <math_constants.h>
#include <cstdint>
#include <mma.h>

using namespace nvcuda;

#define NB     4
#define NSRC   2048
#define NDST   8192
#define CIN    256
#define CSKIP  128
#define CCAT   384
#define HDIM   256
#define COUT   128
#define PDIM   64
#define MTOT   (NB * NDST)          // 32768

#define OUT_ELEMS   (MTOT * COUT)   // 4194304
#define POS_ELEMS   (MTOT * 3)      // 98304

// ---------------------------------------------------------------------------
// Scratch (__device__ globals; no allocations allowed)
// ---------------------------------------------------------------------------
__device__ __nv_bfloat16 g_h1_hi[MTOT * HDIM];    // GEMM2 A hi plane
__device__ __nv_bfloat16 g_h1_lo[MTOT * HDIM];
__device__ __nv_bfloat16 g_w1t_hi[HDIM * CCAT];   // B1 [N=256, K=384]
__device__ __nv_bfloat16 g_w1t_lo[HDIM * CCAT];
__device__ __nv_bfloat16 g_w2t_hi[COUT * HDIM];   // B2 [N=128, K=256]
__device__ __nv_bfloat16 g_w2t_lo[COUT * HDIM];
__device__ float g_gate[NB * COUT];
__device__ int4   g_selI[MTOT];                   // j0, j1, j2, pad
__device__ float4 g_selW[MTOT];                   // w0, w1, w2, inv_den

// fp32 -> bf16 hi/lo split
__device__ __forceinline__ void split_bf16(float v, uint16_t& h, uint16_t& l) {
    __nv_bfloat16 hb = __float2bfloat16_rn(v);
    float r = v - __bfloat162float(hb);
    __nv_bfloat16 lb = __float2bfloat16_rn(r);
    h = __bfloat16_as_ushort(hb);
    l = __bfloat16_as_ushort(lb);
}

// cp.async helpers (sm_80 baseline — legal on sm_103 target)
__device__ __forceinline__ void cp_async16(uint32_t dst, const void* src) {
    asm volatile("cp.async.ca.shared.global [%0], [%1], 16;"
                 :: "r"(dst), "l"(src) : "memory");
}
#define CP_COMMIT() asm volatile("cp.async.commit_group;" ::: "memory")
#define CP_WAIT(n)  asm volatile("cp.async.wait_group %0;" :: "n"(n) : "memory")

// ---------------------------------------------------------------------------
// prep: gate + weight transpose/split + output tail (pos_skip, batch_skip)
// grid = 384 blocks x 256 (covers POS_ELEMS exactly)
// ---------------------------------------------------------------------------
__global__ void prep_kernel(const float* __restrict__ par,
                            const float* __restrict__ Wp,
                            const float* __restrict__ bp,
                            const float* __restrict__ W1,
                            const float* __restrict__ W2,
                            const float* __restrict__ pos_skip,
                            float* __restrict__ out, int mode, int out_size) {
    int i = blockIdx.x * 256 + threadIdx.x;
    if (i < NB * COUT) {
        int b = i >> 7, n = i & 127;
        float acc = bp[n];
        const float* pe = par + b * PDIM;
#pragma unroll
        for (int p = 0; p < PDIM; ++p)
            acc = fmaf(pe[p], Wp[p * COUT + n], acc);
        g_gate[i] = fmaxf(acc, 0.0f);
    }
    if (i < CCAT * HDIM) {
        int k = i / HDIM, n = i % HDIM;
        uint16_t h, l;
        split_bf16(W1[i], h, l);
        g_w1t_hi[n * CCAT + k] = __ushort_as_bfloat16(h);
        g_w1t_lo[n * CCAT + k] = __ushort_as_bfloat16(l);
    }
    if (i < HDIM * COUT) {
        int k = i / COUT, n = i % COUT;
        uint16_t h, l;
        split_bf16(W2[i], h, l);
        g_w2t_hi[n * HDIM + k] = __ushort_as_bfloat16(h);
        g_w2t_lo[n * HDIM + k] = __ushort_as_bfloat16(l);
    }
    // output tail
    if (i < POS_ELEMS && OUT_ELEMS + i < out_size)
        out[OUT_ELEMS + i] = pos_skip[i];
    if (i < MTOT) {
        if (mode == 1) {
            int o = OUT_ELEMS + POS_ELEMS + i;
            if (o < out_size) out[o] = (float)(i >> 13);
        } else if (mode == 2) {
            int o = OUT_ELEMS + POS_ELEMS + 2 * i;
            if (o + 1 < out_size)
                ((long long*)(out + OUT_ELEMS + POS_ELEMS))[i] = (long long)(i >> 13);
        }
    }
}

// ---------------------------------------------------------------------------
// KNN selection only (k=3). Thread-pair per point, even/odd candidate split,
// shfl merge with lowest-index tie-break == sequential-stable top_k.
// d2 rounding bit-matches the reference (R5-validated).
// Writes g_selI / g_selW; interpolation happens inside GEMM1 staging.
// ---------------------------------------------------------------------------
#define PTS_PER_BLK 128

__global__ __launch_bounds__(256)
void knn_select_kernel(const float* __restrict__ pos,
                       const float* __restrict__ pos_skip) {
    __shared__ float4 spos[NSRC];                 // (x, y, z, s2)  32 KB
    const int b   = blockIdx.y;
    const int tid = threadIdx.x;

    const float* sp = pos + (size_t)b * NSRC * 3;
    for (int i = tid; i < NSRC; i += 256) {
        float px = sp[i * 3 + 0];
        float py = sp[i * 3 + 1];
        float pz = sp[i * 3 + 2];
        float s2 = __fmaf_rn(pz, pz, __fmaf_rn(py, py, __fmul_rn(px, px)));
        spos[i] = make_float4(px, py, pz, s2);
    }
    __syncthreads();

    const int slot   = tid >> 1;
    const int parity = tid & 1;
    const int m  = b * NDST + blockIdx.x * PTS_PER_BLK + slot;
    const float dx = pos_skip[m * 3 + 0];
    const float dy = pos_skip[m * 3 + 1];
    const float dz = pos_skip[m * 3 + 2];
    const float dd = __fmaf_rn(dz, dz, __fmaf_rn(dy, dy, __fmul_rn(dx, dx)));

    float a0 = CUDART_INF_F, a1 = CUDART_INF_F, a2 = CUDART_INF_F;
    int   q0 = 0, q1 = 0, q2 = 0;

#pragma unroll 4
    for (int j = parity; j < NSRC; j += 2) {
        float4 c = spos[j];
        float d2 = __fadd_rn(__fadd_rn(dd, c.w),
                   -__fmul_rn(2.0f,
                    __fmaf_rn(dz, c.z, __fmaf_rn(dy, c.y, __fmul_rn(dx, c.x)))));
        bool p0 = d2 < a0, p1 = d2 < a1, p2 = d2 < a2;
        q2 = p1 ? q1 : (p2 ? j  : q2);
        a2 = p1 ? a1 : (p2 ? d2 : a2);
        q1 = p0 ? q0 : (p1 ? j  : q1);
        a1 = p0 ? a0 : (p1 ? d2 : a1);
        q0 = p0 ? j  : q0;
        a0 = p0 ? d2 : a0;
    }

    const unsigned FULL = 0xffffffffu;
    float oa0 = __shfl_down_sync(FULL, a0, 1);
    float oa1 = __shfl_down_sync(FULL, a1, 1);
    float oa2 = __shfl_down_sync(FULL, a2, 1);
    int   oq0 = __shfl_down_sync(FULL, q0, 1);
    int   oq1 = __shfl_down_sync(FULL, q1, 1);
    int   oq2 = __shfl_down_sync(FULL, q2, 1);

    if (parity == 0) {
#pragma unroll
        for (int t = 0; t < 3; ++t) {
            float d  = (t == 0) ? oa0 : (t == 1) ? oa1 : oa2;
            int   jj = (t == 0) ? oq0 : (t == 1) ? oq1 : oq2;
            bool lt0 = (d < a0) || (d == a0 && jj < q0);
            bool lt1 = (d < a1) || (d == a1 && jj < q1);
            bool lt2 = (d < a2) || (d == a2 && jj < q2);
            q2 = lt1 ? q1 : (lt2 ? jj : q2);
            a2 = lt1 ? a1 : (lt2 ? d  : a2);
            q1 = lt0 ? q0 : (lt1 ? jj : q1);
            a1 = lt0 ? a0 : (lt1 ? d  : a1);
            q0 = lt0 ? jj : q0;
            a0 = lt0 ? d  : a0;
        }
        float w0 = __fdiv_rn(1.0f, fmaxf(a0, 1e-16f));
        float w1 = __fdiv_rn(1.0f, fmaxf(a1, 1e-16f));
        float w2 = __fdiv_rn(1.0f, fmaxf(a2, 1e-16f));
        float den = __fadd_rn(__fadd_rn(w0, w1), w2);
        g_selI[m] = make_int4(q0, q1, q2, 0);
        g_selW[m] = make_float4(w0, w1, w2, __fdiv_rn(1.0f, den));
    }
}

// ---------------------------------------------------------------------------
// Shared GEMM tile constants
// ---------------------------------------------------------------------------
#define BK_G   32
#define STRD   40                          // 80B row stride: conflict-free LDSM
#define PL_B   (128 * STRD * 2)            // plane bytes = 10240
#define BUF_B  (4 * PL_B)                  // 4 planes per buffer = 40960
#define CSTR   68                          // epilogue C buffer stride (floats)

// ---------------------------------------------------------------------------
// GEMM1 fused:  h1 = relu( interp_concat(x, x_skip) @ W1 + b1 )
//   A is built on the fly during staging: chunks 0-7 gather x rows by the
//   KNN-selected indices and interpolate (same formula as R10/R11), chunks
//   8-11 read x_skip directly. fp32 -> split bf16 -> STS into MMA planes.
//   B staged via cp.async. 3-term split MMA, fp32 accumulate.
// ---------------------------------------------------------------------------
__global__ __launch_bounds__(256, 2)
void gemm1_fused_kernel(const float* __restrict__ x,
                        const float* __restrict__ x_skip,
                        const __nv_bfloat16* __restrict__ Bh,
                        const __nv_bfloat16* __restrict__ Bl,
                        const float* __restrict__ bias) {
    constexpr int NC = CCAT / BK_G;        // 12
    extern __shared__ char smem[];
    const uint32_t sbase = (uint32_t)__cvta_generic_to_shared(smem);

    const int tid  = threadIdx.x;
    const int w    = tid >> 5;
    const int lane = tid & 31;
    const int bm   = blockIdx.y * 128;
    const int bn   = blockIdx.x * 128;
    const int wm   = (w & 3) * 32;
    const int wn   = (w >> 2) * 64;

    // per-thread A-staging identity: row + 16-elem segment
    const int arow = tid >> 1;
    const int aseg = tid & 1;
    const int grow = bm + arow;                    // global dst row
    const int batch = bm >> 13;                    // whole CTA same batch
    const size_t xbase = (size_t)batch * NSRC;

    const int4   sI = g_selI[grow];
    const float4 sW = g_selW[grow];
    const float* xr0 = x + (xbase + sI.x) * CIN;
    const float* xr1 = x + (xbase + sI.y) * CIN;
    const float* xr2 = x + (xbase + sI.z) * CIN;
    const float* xsk = x_skip + (size_t)grow * CSKIP;

    auto stageA = [&](int kc, int buf) {
        float v[16];
        if (kc < CIN / BK_G) {                     // interp region
            const int col0 = kc * BK_G + aseg * 16;
#pragma unroll
            for (int q = 0; q < 4; ++q) {
                float4 r0 = *(const float4*)(xr0 + col0 + q * 4);
                float4 r1 = *(const float4*)(xr1 + col0 + q * 4);
                float4 r2 = *(const float4*)(xr2 + col0 + q * 4);
                const float* p0 = &r0.x;
                const float* p1 = &r1.x;
                const float* p2 = &r2.x;
#pragma unroll
                for (int e = 0; e < 4; ++e) {
                    float num = __fadd_rn(__fadd_rn(__fmul_rn(sW.x, p0[e]),
                                                    __fmul_rn(sW.y, p1[e])),
                                          __fmul_rn(sW.z, p2[e]));
                    v[q * 4 + e] = __fmul_rn(num, sW.w);
                }
            }
        } else {                                   // x_skip region
            const int col0 = kc * BK_G - CIN + aseg * 16;
#pragma unroll
            for (int q = 0; q < 4; ++q) {
                float4 s = *(const float4*)(xsk + col0 + q * 4);
                v[q * 4 + 0] = s.x;
                v[q * 4 + 1] = s.y;
                v[q * 4 + 2] = s.z;
                v[q * 4 + 3] = s.w;
            }
        }
        uint32_t hp[8], lp[8];
#pragma unroll
        for (int e = 0; e < 16; e += 2) {
            uint16_t h0, l0, h1, l1;
            split_bf16(v[e],     h0, l0);
            split_bf16(v[e + 1], h1, l1);
            hp[e >> 1] = (uint32_t)h0 | ((uint32_t)h1 << 16);
            lp[e >> 1] = (uint32_t)l0 | ((uint32_t)l1 << 16);
        }
        char* base = smem + buf * BUF_B;
        uint4* dh = (uint4*)(base + arow * (STRD * 2) + aseg * 32);
        uint4* dl = (uint4*)(base + PL_B + arow * (STRD * 2) + aseg * 32);
        dh[0] = make_uint4(hp[0], hp[1], hp[2], hp[3]);
        dh[1] = make_uint4(hp[4], hp[5], hp[6], hp[7]);
        dl[0] = make_uint4(lp[0], lp[1], lp[2], lp[3]);
        dl[1] = make_uint4(lp[4], lp[5], lp[6], lp[7]);
    };

    auto stageB = [&](int kc, int buf) {
#pragma unroll
        for (int u = tid; u < 1024; u += 256) {
            const int plane = u >> 9;
            const int idx   = u & 511;
            const int row   = idx >> 2;
            const int c     = idx & 3;
            const __nv_bfloat16* P = plane ? Bl : Bh;
            const __nv_bfloat16* gsrc =
                P + (size_t)(bn + row) * CCAT + kc * BK_G + c * 8;
            uint32_t sdst = sbase + buf * BUF_B + (2 + plane) * PL_B +
                            row * (STRD * 2) + c * 16;
            cp_async16(sdst, gsrc);
        }
    };

    wmma::fragment<wmma::accumulator, 16, 16, 16, float> acc[2][4];
#pragma unroll
    for (int i = 0; i < 2; ++i)
#pragma unroll
        for (int j = 0; j < 4; ++j)
            wmma::fill_fragment(acc[i][j], 0.0f);

    stageB(0, 0);
    CP_COMMIT();
    stageA(0, 0);
    CP_WAIT(0);
    __syncthreads();

    for (int kc = 0; kc < NC; ++kc) {
        if (kc + 1 < NC) {
            stageB(kc + 1, (kc + 1) & 1);
            CP_COMMIT();
            stageA(kc + 1, (kc + 1) & 1);
        }

        const __nv_bfloat16* sb =
            (const __nv_bfloat16*)(smem + (kc & 1) * BUF_B);
        const __nv_bfloat16* sAh = sb;
        const __nv_bfloat16* sAl = sb + 128 * STRD;
        const __nv_bfloat16* sBh = sb + 2 * 128 * STRD;
        const __nv_bfloat16* sBl = sb + 3 * 128 * STRD;

#pragma unroll
        for (int kk = 0; kk < BK_G; kk += 16) {
            wmma::fragment<wmma::matrix_a, 16, 16, 16, __nv_bfloat16,
                           wmma::row_major> a_h[2], a_l[2];
#pragma unroll
            for (int i = 0; i < 2; ++i) {
                wmma::load_matrix_sync(a_h[i], sAh + (wm + i * 16) * STRD + kk, STRD);
                wmma::load_matrix_sync(a_l[i], sAl + (wm + i * 16) * STRD + kk, STRD);
            }
#pragma unroll
            for (int j = 0; j < 4; ++j) {
                wmma::fragment<wmma::matrix_b, 16, 16, 16, __nv_bfloat16,
                               wmma::col_major> b_h, b_l;
                wmma::load_matrix_sync(b_h, sBh + (wn + j * 16) * STRD + kk, STRD);
                wmma::load_matrix_sync(b_l, sBl + (wn + j * 16) * STRD + kk, STRD);
                wmma::mma_sync(acc[0][j], a_h[0], b_h, acc[0][j]);
                wmma::mma_sync(acc[1][j], a_h[1], b_h, acc[1][j]);
                wmma::mma_sync(acc[0][j], a_h[0], b_l, acc[0][j]);
                wmma::mma_sync(acc[1][j], a_h[1], b_l, acc[1][j]);
                wmma::mma_sync(acc[0][j], a_l[0], b_h, acc[0][j]);
                wmma::mma_sync(acc[1][j], a_l[1], b_h, acc[1][j]);
            }
        }
        if (kc + 1 < NC) CP_WAIT(0);
        __syncthreads();
    }

    // epilogue: bias + relu + split -> g_h1 planes
    float* cw = (float*)smem + w * (32 * CSTR);
#pragma unroll
    for (int i = 0; i < 2; ++i)
#pragma unroll
        for (int j = 0; j < 4; ++j)
            wmma::store_matrix_sync(cw + i * 16 * CSTR + j * 16, acc[i][j],
                                    CSTR, wmma::mem_row_major);
    __syncwarp();

    const int m = bm + wm + lane;
    const int ncol0 = bn + wn;
    uint32_t* dh = (uint32_t*)(g_h1_hi + (size_t)m * HDIM + ncol0);
    uint32_t* dl = (uint32_t*)(g_h1_lo + (size_t)m * HDIM + ncol0);
#pragma unroll
    for (int c = 0; c < 64; c += 2) {
        float v0 = fmaxf(cw[lane * CSTR + c]     + bias[ncol0 + c],     0.0f);
        float v1 = fmaxf(cw[lane * CSTR + c + 1] + bias[ncol0 + c + 1], 0.0f);
        uint16_t h0, l0, h1, l1;
        split_bf16(v0, h0, l0);
        split_bf16(v1, h1, l1);
        dh[c >> 1] = (uint32_t)h0 | ((uint32_t)h1 << 16);
        dl[c >> 1] = (uint32_t)l0 | ((uint32_t)l1 << 16);
    }
}

// ---------------------------------------------------------------------------
// GEMM2 (unchanged R11 structure): out = (h1 @ W2 + b2) * gate[batch]
// ---------------------------------------------------------------------------
__global__ __launch_bounds__(256, 2)
void gemm2_kernel(const __nv_bfloat16* __restrict__ Ah,
                  const __nv_bfloat16* __restrict__ Al,
                  const __nv_bfloat16* __restrict__ Bh,
                  const __nv_bfloat16* __restrict__ Bl,
                  const float* __restrict__ bias,
                  float* __restrict__ outp) {
    constexpr int KTOT = HDIM;
    constexpr int N    = COUT;
    constexpr int NC   = KTOT / BK_G;      // 8
    extern __shared__ char smem[];
    const uint32_t sbase = (uint32_t)__cvta_generic_to_shared(smem);

    const int tid  = threadIdx.x;
    const int w    = tid >> 5;
    const int lane = tid & 31;
    const int bm   = blockIdx.y * 128;
    const int bn   = blockIdx.x * 128;
    const int wm   = (w & 3) * 32;
    const int wn   = (w >> 2) * 64;

    auto stage = [&](int kc, int buf) {
#pragma unroll
        for (int u = tid; u < 2048; u += 256) {
            const int plane = u >> 9;
            const int idx   = u & 511;
            const int row   = idx >> 2;
            const int c     = idx & 3;
            const __nv_bfloat16* P =
                (plane == 0) ? Ah : (plane == 1) ? Al : (plane == 2) ? Bh : Bl;
            const int grow = (plane < 2) ? (bm + row) : (bn + row);
            const __nv_bfloat16* gsrc =
                P + (size_t)grow * KTOT + kc * BK_G + c * 8;
            uint32_t sdst = sbase + buf * BUF_B + plane * PL_B +
                            row * (STRD * 2) + c * 16;
            cp_async16(sdst, gsrc);
        }
    };

    wmma::fragment<wmma::accumulator, 16, 16, 16, float> acc[2][4];
#pragma unroll
    for (int i = 0; i < 2; ++i)
#pragma unroll
        for (int j = 0; j < 4; ++j)
            wmma::fill_fragment(acc[i][j], 0.0f);

    stage(0, 0);
    CP_COMMIT();

    for (int kc = 0; kc < NC; ++kc) {
        if (kc + 1 < NC) {
            stage(kc + 1, (kc + 1) & 1);
            CP_COMMIT();
            CP_WAIT(1);
        } else {
            CP_WAIT(0);
        }
        __syncthreads();

        const __nv_bfloat16* sb =
            (const __nv_bfloat16*)(smem + (kc & 1) * BUF_B);
        const __nv_bfloat16* sAh = sb;
        const __nv_bfloat16* sAl = sb + 128 * STRD;
        const __nv_bfloat16* sBh = sb + 2 * 128 * STRD;
        const __nv_bfloat16* sBl = sb + 3 * 128 * STRD;

#pragma unroll
        for (int kk = 0; kk < BK_G; kk += 16) {
            wmma::fragment<wmma::matrix_a, 16, 16, 16, __nv_bfloat16,
                           wmma::row_major> a_h[2], a_l[2];
#pragma unroll
            for (int i = 0; i < 2; ++i) {
                wmma::load_matrix_sync(a_h[i], sAh + (wm + i * 16) * STRD + kk, STRD);
                wmma::load_matrix_sync(a_l[i], sAl + (wm + i * 16) * STRD + kk, STRD);
            }
#pragma unroll
            for (int j = 0; j < 4; ++j) {
                wmma::fragment<wmma::matrix_b, 16, 16, 16, __nv_bfloat16,
                               wmma::col_major> b_h, b_l;
                wmma::load_matrix_sync(b_h, sBh + (wn + j * 16) * STRD + kk, STRD);
                wmma::load_matrix_sync(b_l, sBl + (wn + j * 16) * STRD + kk, STRD);
                wmma::mma_sync(acc[0][j], a_h[0], b_h, acc[0][j]);
                wmma::mma_sync(acc[1][j], a_h[1], b_h, acc[1][j]);
                wmma::mma_sync(acc[0][j], a_h[0], b_l, acc[0][j]);
                wmma::mma_sync(acc[1][j], a_h[1], b_l, acc[1][j]);
                wmma::mma_sync(acc[0][j], a_l[0], b_h, acc[0][j]);
                wmma::mma_sync(acc[1][j], a_l[1], b_h, acc[1][j]);
            }
        }
        __syncthreads();
    }

    float* cw = (float*)smem + w * (32 * CSTR);
#pragma unroll
    for (int i = 0; i < 2; ++i)
#pragma unroll
        for (int j = 0; j < 4; ++j)
            wmma::store_matrix_sync(cw + i * 16 * CSTR + j * 16, acc[i][j],
                                    CSTR, wmma::mem_row_major);
    __syncwarp();

    const int m = bm + wm + lane;
    const int ncol0 = bn + wn;
    const int batch = m >> 13;
    const float* gt = g_gate + batch * COUT;
    float4* dst = (float4*)(outp + (size_t)m * N + ncol0);
#pragma unroll
    for (int c = 0; c < 64; c += 4) {
        float4 o;
        o.x = (cw[lane * CSTR + c]     + bias[ncol0 + c])     * gt[ncol0 + c];
        o.y = (cw[lane * CSTR + c + 1] + bias[ncol0 + c + 1]) * gt[ncol0 + c + 1];
        o.z = (cw[lane * CSTR + c + 2] + bias[ncol0 + c + 2]) * gt[ncol0 + c + 2];
        o.w = (cw[lane * CSTR + c + 3] + bias[ncol0 + c + 3]) * gt[ncol0 + c + 3];
        dst[c >> 2] = o;
    }
}

// ---------------------------------------------------------------------------
extern "C" void kernel_launch(void* const* d_in, const int* in_sizes, int n_in,
                              void* d_out, int out_size) {
    const float* par      = (const float*)d_in[0];
    const float* x        = (const float*)d_in[1];
    const float* pos      = (const float*)d_in[2];
    const float* x_skip   = (const float*)d_in[3];
    const float* pos_skip = (const float*)d_in[4];
    const float* W1       = (const float*)d_in[5];
    const float* b1       = (const float*)d_in[6];
    const float* W2       = (const float*)d_in[7];
    const float* b2       = (const float*)d_in[8];
    const float* Wp       = (const float*)d_in[9];
    const float* bp       = (const float*)d_in[10];
    float* out = (float*)d_out;

    __nv_bfloat16 *p_hh, *p_hl, *p_w1h, *p_w1l, *p_w2h, *p_w2l;
    cudaGetSymbolAddress((void**)&p_hh,  g_h1_hi);
    cudaGetSymbolAddress((void**)&p_hl,  g_h1_lo);
    cudaGetSymbolAddress((void**)&p_w1h, g_w1t_hi);
    cudaGetSymbolAddress((void**)&p_w1l, g_w1t_lo);
    cudaGetSymbolAddress((void**)&p_w2h, g_w2t_hi);
    cudaGetSymbolAddress((void**)&p_w2l, g_w2t_lo);

    constexpr int SMEM_G = 2 * BUF_B;   // 81920
    cudaFuncSetAttribute(gemm1_fused_kernel,
                         cudaFuncAttributeMaxDynamicSharedMemorySize, SMEM_G);
    cudaFuncSetAttribute(gemm2_kernel,
                         cudaFuncAttributeMaxDynamicSharedMemorySize, SMEM_G);

    const int tail = out_size - OUT_ELEMS;
    int mode = 0;
    if (tail >= POS_ELEMS + 2 * MTOT)      mode = 2;
    else if (tail >= POS_ELEMS + MTOT)     mode = 1;

    prep_kernel<<<(POS_ELEMS + 255) / 256, 256>>>(par, Wp, bp, W1, W2,
                                                  pos_skip, out, mode, out_size);

    dim3 kg(NDST / PTS_PER_BLK, NB);       // (64, 4)
    knn_select_kernel<<<kg, 256>>>(pos, pos_skip);

    dim3 g1(HDIM / 128, MTOT / 128);       // (2, 256)
    gemm1_fused_kernel<<<g1, 256, SMEM_G>>>(x, x_skip, p_w1h, p_w1l, b1);

    dim3 g2(COUT / 128, MTOT / 128);       // (1, 256)
    gemm2_kernel<<<g2, 256, SMEM_G>>>(p_hh, p_hl, p_w2h, p_w2l, b2, out);
}